// round 2
// baseline (speedup 1.0000x reference)
#include <cuda_runtime.h>
#include <math.h>

#define DM 1024
#define NH 16
#define DK 64
#define B_ 2
#define S_ 2048
#define MTOT (B_*S_)   // 4096

// scratch (device globals: allocation-free)
__device__ float g_Q[B_*S_*DM];
__device__ float g_K[B_*S_*DM];
__device__ float g_V[B_*S_*DM];
__device__ float g_A[B_*S_*DM];

// ---------------------------------------------------------------------------
// SGEMM: Y[M,N] = X[M,K] @ W[N,K]^T   (128x128 block, 8x8 per thread, BK=8)
// ---------------------------------------------------------------------------
#define GBM 128
#define GBN 128
#define GBK 8
#define GPAD 132

__global__ __launch_bounds__(256)
void sgemm_xwt(const float* __restrict__ X, const float* __restrict__ W,
               float* __restrict__ Y, int M, int N, int K)
{
    __shared__ __align__(16) float As[GBK * GPAD];
    __shared__ __align__(16) float Bs[GBK * GPAD];

    const int tid = threadIdx.x;
    const int tx = tid & 15;
    const int ty = tid >> 4;
    const int bm = blockIdx.y * GBM;
    const int bn = blockIdx.x * GBN;

    const int lr = tid >> 1;          // 0..127
    const int lc = (tid & 1) * 4;     // 0 or 4

    const float* Xp = X + (size_t)(bm + lr) * K + lc;
    const float* Wp = W + (size_t)(bn + lr) * K + lc;

    float acc[8][8];
#pragma unroll
    for (int i = 0; i < 8; i++)
#pragma unroll
        for (int j = 0; j < 8; j++) acc[i][j] = 0.f;

    for (int k0 = 0; k0 < K; k0 += GBK) {
        float4 a = *(const float4*)(Xp + k0);
        float4 b = *(const float4*)(Wp + k0);
        As[(lc + 0) * GPAD + lr] = a.x;
        As[(lc + 1) * GPAD + lr] = a.y;
        As[(lc + 2) * GPAD + lr] = a.z;
        As[(lc + 3) * GPAD + lr] = a.w;
        Bs[(lc + 0) * GPAD + lr] = b.x;
        Bs[(lc + 1) * GPAD + lr] = b.y;
        Bs[(lc + 2) * GPAD + lr] = b.z;
        Bs[(lc + 3) * GPAD + lr] = b.w;
        __syncthreads();

#pragma unroll
        for (int k = 0; k < GBK; k++) {
            float ra[8], rb[8];
            *(float4*)&ra[0] = *(float4*)&As[k * GPAD + ty * 8];
            *(float4*)&ra[4] = *(float4*)&As[k * GPAD + ty * 8 + 4];
            *(float4*)&rb[0] = *(float4*)&Bs[k * GPAD + tx * 8];
            *(float4*)&rb[4] = *(float4*)&Bs[k * GPAD + tx * 8 + 4];
#pragma unroll
            for (int i = 0; i < 8; i++)
#pragma unroll
                for (int j = 0; j < 8; j++)
                    acc[i][j] = fmaf(ra[i], rb[j], acc[i][j]);
        }
        __syncthreads();
    }

#pragma unroll
    for (int i = 0; i < 8; i++) {
        float* yp = Y + (size_t)(bm + ty * 8 + i) * N + bn + tx * 8;
        *(float4*)yp       = make_float4(acc[i][0], acc[i][1], acc[i][2], acc[i][3]);
        *(float4*)(yp + 4) = make_float4(acc[i][4], acc[i][5], acc[i][6], acc[i][7]);
    }
}

// ---------------------------------------------------------------------------
// RoPE on Q and K in place. Pair (2p, 2p+1), freq index p, inv = theta^(-2p/64).
// Angle computed in fp32 (matching the reference's fp32 multiply), trig in
// double (immune to --use_fast_math), rounded back to fp32.
// ---------------------------------------------------------------------------
__global__ void rope_kernel(float* __restrict__ Q, float* __restrict__ Kk,
                            const int* __restrict__ pos)
{
    int idx = blockIdx.x * blockDim.x + threadIdx.x;
    const int total = B_ * S_ * DM / 2;
    if (idx >= total) return;

    int p    = idx & 31;          // pair index (DK/2 = 32)
    int rest = idx >> 5;
    int h    = rest & (NH - 1);
    int row  = rest >> 4;
    int s    = row & (S_ - 1);

    float posf = (float)pos[s];
    double e   = (double)(2 * p) / (double)DK;
    float inv  = (float)exp(-e * log(10000.0));
    float ang  = posf * inv;               // fp32 angle, as the reference computes
    float c    = (float)cos((double)ang);  // accurate trig regardless of fast-math
    float sn   = (float)sin((double)ang);

    size_t off = (size_t)row * DM + h * DK + 2 * p;
    float q1 = Q[off], q2 = Q[off + 1];
    Q[off]     = q1 * c - q2 * sn;
    Q[off + 1] = q1 * sn + q2 * c;
    float k1 = Kk[off], k2 = Kk[off + 1];
    Kk[off]     = k1 * c - k2 * sn;
    Kk[off + 1] = k1 * sn + k2 * c;
}

// ---------------------------------------------------------------------------
// Causal flash attention. One CTA = 64 queries of one (b,h).
// Qs,Ks stored [d][m] (transposed), Vs [n][d], Ps [n][m]. Online softmax.
// ---------------------------------------------------------------------------
#define APAD 68
#define ASM_BYTES (4 * 64 * APAD * 4)   // 69632

__global__ __launch_bounds__(256)
void attn_kernel(const float* __restrict__ Qg, const float* __restrict__ Kg,
                 const float* __restrict__ Vg, float* __restrict__ Og)
{
    extern __shared__ __align__(16) float smbuf[];
    float* Qs = smbuf;                  // [64][APAD]  (d, m)
    float* Ks = smbuf + 64 * APAD;      // [64][APAD]  (d, n)
    float* Vs = smbuf + 2 * 64 * APAD;  // [64][APAD]  (n, d)
    float* Ps = smbuf + 3 * 64 * APAD;  // [64][APAD]  (n, m)

    const int tid = threadIdx.x;
    const int tx = tid & 15;
    const int ty = tid >> 4;
    const int qb = blockIdx.x;
    const int bh = blockIdx.y;
    const int b  = bh >> 4;
    const int h  = bh & 15;
    const size_t base = (size_t)b * S_ * DM + (size_t)h * DK;
    const float scale = 0.125f;         // 1/sqrt(64)

    // load Q tile transposed: Qs[d][m]
#pragma unroll
    for (int i4 = 0; i4 < 4; i4++) {
        int e  = tid + i4 * 256;
        int r  = e >> 4;
        int d4 = (e & 15) << 2;
        float4 g = *(const float4*)&Qg[base + (size_t)(qb * 64 + r) * DM + d4];
        Qs[(d4 + 0) * APAD + r] = g.x;
        Qs[(d4 + 1) * APAD + r] = g.y;
        Qs[(d4 + 2) * APAD + r] = g.z;
        Qs[(d4 + 3) * APAD + r] = g.w;
    }

    float o[4][4];
    float mrow[4], lrow[4];
#pragma unroll
    for (int i = 0; i < 4; i++) {
        mrow[i] = -1e30f;
        lrow[i] = 0.f;
#pragma unroll
        for (int j = 0; j < 4; j++) o[i][j] = 0.f;
    }

    for (int kb = 0; kb <= qb; kb++) {
        __syncthreads();

        // load K transposed, V direct
#pragma unroll
        for (int i4 = 0; i4 < 4; i4++) {
            int e  = tid + i4 * 256;
            int r  = e >> 4;
            int d4 = (e & 15) << 2;
            size_t goff = base + (size_t)(kb * 64 + r) * DM + d4;
            float4 g = *(const float4*)&Kg[goff];
            Ks[(d4 + 0) * APAD + r] = g.x;
            Ks[(d4 + 1) * APAD + r] = g.y;
            Ks[(d4 + 2) * APAD + r] = g.z;
            Ks[(d4 + 3) * APAD + r] = g.w;
            float4 v = *(const float4*)&Vg[goff];
            *(float4*)&Vs[r * APAD + d4] = v;
        }
        __syncthreads();

        // scores
        float s[4][4];
#pragma unroll
        for (int i = 0; i < 4; i++)
#pragma unroll
            for (int j = 0; j < 4; j++) s[i][j] = 0.f;

#pragma unroll
        for (int d = 0; d < 64; d++) {
            float4 qv = *(float4*)&Qs[d * APAD + ty * 4];
            float4 kv = *(float4*)&Ks[d * APAD + tx * 4];
            float qa[4] = {qv.x, qv.y, qv.z, qv.w};
            float ka[4] = {kv.x, kv.y, kv.z, kv.w};
#pragma unroll
            for (int i = 0; i < 4; i++)
#pragma unroll
                for (int j = 0; j < 4; j++)
                    s[i][j] = fmaf(qa[i], ka[j], s[i][j]);
        }

        // scale + causal mask using GLOBAL indices (correct for every block)
#pragma unroll
        for (int i = 0; i < 4; i++) {
            int gq = qb * 64 + ty * 4 + i;
#pragma unroll
            for (int j = 0; j < 4; j++) {
                int gk = kb * 64 + tx * 4 + j;
                s[i][j] = (gk > gq) ? -1e30f : s[i][j] * scale;
            }
        }

        // online softmax update per row
#pragma unroll
        for (int i = 0; i < 4; i++) {
            float rmax = fmaxf(fmaxf(s[i][0], s[i][1]), fmaxf(s[i][2], s[i][3]));
#pragma unroll
            for (int msk = 1; msk < 16; msk <<= 1)
                rmax = fmaxf(rmax, __shfl_xor_sync(0xffffffffu, rmax, msk));
            float mnew = fmaxf(mrow[i], rmax);
            float rsum = 0.f;
#pragma unroll
            for (int j = 0; j < 4; j++) {
                s[i][j] = expf(s[i][j] - mnew);
                rsum += s[i][j];
            }
#pragma unroll
            for (int msk = 1; msk < 16; msk <<= 1)
                rsum += __shfl_xor_sync(0xffffffffu, rsum, msk);
            float alpha = expf(mrow[i] - mnew);
            lrow[i] = lrow[i] * alpha + rsum;
            mrow[i] = mnew;
#pragma unroll
            for (int j = 0; j < 4; j++) o[i][j] *= alpha;
        }

        // write P transposed: Ps[n][m]
#pragma unroll
        for (int i = 0; i < 4; i++)
#pragma unroll
            for (int j = 0; j < 4; j++)
                Ps[(tx * 4 + j) * APAD + ty * 4 + i] = s[i][j];
        __syncthreads();

        // o += P @ V
#pragma unroll
        for (int n = 0; n < 64; n++) {
            float4 pv = *(float4*)&Ps[n * APAD + ty * 4];
            float4 vv = *(float4*)&Vs[n * APAD + tx * 4];
            float pa[4] = {pv.x, pv.y, pv.z, pv.w};
            float va[4] = {vv.x, vv.y, vv.z, vv.w};
#pragma unroll
            for (int i = 0; i < 4; i++)
#pragma unroll
                for (int j = 0; j < 4; j++)
                    o[i][j] = fmaf(pa[i], va[j], o[i][j]);
        }
    }

    // epilogue
#pragma unroll
    for (int i = 0; i < 4; i++) {
        float inv = 1.0f / lrow[i];
        float* op = Og + base + (size_t)(qb * 64 + ty * 4 + i) * DM + tx * 4;
        *(float4*)op = make_float4(o[i][0] * inv, o[i][1] * inv,
                                   o[i][2] * inv, o[i][3] * inv);
    }
}

// ---------------------------------------------------------------------------
extern "C" void kernel_launch(void* const* d_in, const int* in_sizes, int n_in,
                              void* d_out, int out_size)
{
    // Identify inputs by size:
    //   x   = 4,194,304 elts; token_positions = 2,048; weights = 1,048,576 each.
    // Case A (setup_inputs dict order):  x, pos, Wq, Wk, Wv, Wo
    // Case B (name-sorted order):        Wk, Wo, Wq, Wv, pos, x
    const float *x, *Wq, *Wk, *Wv, *Wo;
    const int* pos;
    if (in_sizes[0] == MTOT * DM) {            // Case A
        x   = (const float*)d_in[0];
        pos = (const int*)  d_in[1];
        Wq  = (const float*)d_in[2];
        Wk  = (const float*)d_in[3];
        Wv  = (const float*)d_in[4];
        Wo  = (const float*)d_in[5];
    } else {                                   // Case B
        Wk  = (const float*)d_in[0];
        Wo  = (const float*)d_in[1];
        Wq  = (const float*)d_in[2];
        Wv  = (const float*)d_in[3];
        pos = (const int*)  d_in[4];
        x   = (const float*)d_in[5];
    }
    float* out = (float*)d_out;

    float *Q, *K, *V, *A;
    cudaGetSymbolAddress((void**)&Q, g_Q);
    cudaGetSymbolAddress((void**)&K, g_K);
    cudaGetSymbolAddress((void**)&V, g_V);
    cudaGetSymbolAddress((void**)&A, g_A);

    dim3 gg(DM / GBN, MTOT / GBM);   // (8, 32)

    sgemm_xwt<<<gg, 256>>>(x, Wq, Q, MTOT, DM, DM);
    sgemm_xwt<<<gg, 256>>>(x, Wk, K, MTOT, DM, DM);
    sgemm_xwt<<<gg, 256>>>(x, Wv, V, MTOT, DM, DM);

    int total = B_ * S_ * DM / 2;
    rope_kernel<<<(total + 255) / 256, 256>>>(Q, K, pos);

    cudaFuncSetAttribute(attn_kernel, cudaFuncAttributeMaxDynamicSharedMemorySize,
                         ASM_BYTES);
    attn_kernel<<<dim3(S_ / 64, B_ * NH), 256, ASM_BYTES>>>(Q, K, V, A);

    sgemm_xwt<<<gg, 256>>>(A, Wo, out, MTOT, DM, DM);
}

// round 3
// speedup vs baseline: 1.2718x; 1.2718x over previous
#include <cuda_runtime.h>
#include <math.h>

#define DM 1024
#define NH 16
#define DK 64
#define B_ 2
#define S_ 2048
#define MTOT (B_*S_)   // 4096

// scratch (device globals: allocation-free)
__device__ float g_Q[B_*S_*DM];
__device__ float g_K[B_*S_*DM];
__device__ float g_V[B_*S_*DM];
__device__ float g_A[B_*S_*DM];
__device__ float2 g_cs[S_ * (DK/2)];   // cos/sin table [s][p]

// ---------------------------------------------------------------------------
// Build cos/sin table: 65536 threads, one fp64 trig pair each (~5us).
// inv_freq in double then rounded to fp32 (ulp-matches the fp32 reference);
// angle = posf * inv in fp32 (as the reference computes); trig in double
// (immune to --use_fast_math), rounded back to fp32.
// ---------------------------------------------------------------------------
__global__ void build_cs_kernel(const int* __restrict__ pos,
                                float2* __restrict__ cs)
{
    int idx = blockIdx.x * blockDim.x + threadIdx.x;
    if (idx >= S_ * (DK/2)) return;
    int s = idx >> 5;             // DK/2 = 32
    int p = idx & 31;

    float posf = (float)pos[s];
    double e   = (double)(2 * p) / (double)DK;
    float inv  = (float)exp(-e * log(10000.0));
    float ang  = posf * inv;
    cs[idx] = make_float2((float)cos((double)ang), (float)sin((double)ang));
}

// ---------------------------------------------------------------------------
// SGEMM: Y[M,N] = X[M,K] @ W[N,K]^T  (128x128 block, 8x8/thread, BK=8,
// double-buffered smem). Optional fused RoPE on the output (pairs = adjacent
// even/odd columns, which live in the same thread's accumulators).
// ---------------------------------------------------------------------------
#define GBM 128
#define GBN 128
#define GBK 8
#define GPAD 132

template<bool ROPE>
__global__ __launch_bounds__(256)
void sgemm_xwt(const float* __restrict__ X, const float* __restrict__ W,
               float* __restrict__ Y, const float2* __restrict__ cs,
               int M, int N, int K)
{
    __shared__ __align__(16) float As[2][GBK * GPAD];
    __shared__ __align__(16) float Bs[2][GBK * GPAD];

    const int tid = threadIdx.x;
    const int tx = tid & 15;
    const int ty = tid >> 4;
    const int bm = blockIdx.y * GBM;
    const int bn = blockIdx.x * GBN;

    const int lr = tid >> 1;          // 0..127
    const int lc = (tid & 1) * 4;     // 0 or 4

    const float* Xp = X + (size_t)(bm + lr) * K + lc;
    const float* Wp = W + (size_t)(bn + lr) * K + lc;

    float acc[8][8];
#pragma unroll
    for (int i = 0; i < 8; i++)
#pragma unroll
        for (int j = 0; j < 8; j++) acc[i][j] = 0.f;

    // prologue: stage tile 0
    {
        float4 a = *(const float4*)(Xp);
        float4 b = *(const float4*)(Wp);
        As[0][(lc + 0) * GPAD + lr] = a.x;
        As[0][(lc + 1) * GPAD + lr] = a.y;
        As[0][(lc + 2) * GPAD + lr] = a.z;
        As[0][(lc + 3) * GPAD + lr] = a.w;
        Bs[0][(lc + 0) * GPAD + lr] = b.x;
        Bs[0][(lc + 1) * GPAD + lr] = b.y;
        Bs[0][(lc + 2) * GPAD + lr] = b.z;
        Bs[0][(lc + 3) * GPAD + lr] = b.w;
    }
    __syncthreads();

    int cur = 0;
    for (int k0 = GBK; k0 < K; k0 += GBK, cur ^= 1) {
        // issue next-tile global loads before compute
        float4 a = *(const float4*)(Xp + k0);
        float4 b = *(const float4*)(Wp + k0);

#pragma unroll
        for (int k = 0; k < GBK; k++) {
            float ra[8], rb[8];
            *(float4*)&ra[0] = *(float4*)&As[cur][k * GPAD + ty * 8];
            *(float4*)&ra[4] = *(float4*)&As[cur][k * GPAD + ty * 8 + 4];
            *(float4*)&rb[0] = *(float4*)&Bs[cur][k * GPAD + tx * 8];
            *(float4*)&rb[4] = *(float4*)&Bs[cur][k * GPAD + tx * 8 + 4];
#pragma unroll
            for (int i = 0; i < 8; i++)
#pragma unroll
                for (int j = 0; j < 8; j++)
                    acc[i][j] = fmaf(ra[i], rb[j], acc[i][j]);
        }

        int nxt = cur ^ 1;
        As[nxt][(lc + 0) * GPAD + lr] = a.x;
        As[nxt][(lc + 1) * GPAD + lr] = a.y;
        As[nxt][(lc + 2) * GPAD + lr] = a.z;
        As[nxt][(lc + 3) * GPAD + lr] = a.w;
        Bs[nxt][(lc + 0) * GPAD + lr] = b.x;
        Bs[nxt][(lc + 1) * GPAD + lr] = b.y;
        Bs[nxt][(lc + 2) * GPAD + lr] = b.z;
        Bs[nxt][(lc + 3) * GPAD + lr] = b.w;
        __syncthreads();
    }

    // last tile
#pragma unroll
    for (int k = 0; k < GBK; k++) {
        float ra[8], rb[8];
        *(float4*)&ra[0] = *(float4*)&As[cur][k * GPAD + ty * 8];
        *(float4*)&ra[4] = *(float4*)&As[cur][k * GPAD + ty * 8 + 4];
        *(float4*)&rb[0] = *(float4*)&Bs[cur][k * GPAD + tx * 8];
        *(float4*)&rb[4] = *(float4*)&Bs[cur][k * GPAD + tx * 8 + 4];
#pragma unroll
        for (int i = 0; i < 8; i++)
#pragma unroll
            for (int j = 0; j < 8; j++)
                acc[i][j] = fmaf(ra[i], rb[j], acc[i][j]);
    }

    // epilogue (+ optional fused RoPE)
    const int col0 = bn + tx * 8;            // even; 8 consecutive cols = 4 pairs
#pragma unroll
    for (int i = 0; i < 8; i++) {
        if (ROPE) {
            int m = bm + ty * 8 + i;
            int s = m & (S_ - 1);
            int p0 = (col0 & (DK - 1)) >> 1;  // first pair index within head
            const float2* csr = cs + s * (DK/2) + p0;
#pragma unroll
            for (int pr = 0; pr < 4; pr++) {
                float2 cspr = csr[pr];
                float x1 = acc[i][2*pr], x2 = acc[i][2*pr + 1];
                acc[i][2*pr]     = x1 * cspr.x - x2 * cspr.y;
                acc[i][2*pr + 1] = x1 * cspr.y + x2 * cspr.x;
            }
        }
        float* yp = Y + (size_t)(bm + ty * 8 + i) * N + col0;
        *(float4*)yp       = make_float4(acc[i][0], acc[i][1], acc[i][2], acc[i][3]);
        *(float4*)(yp + 4) = make_float4(acc[i][4], acc[i][5], acc[i][6], acc[i][7]);
    }
}

// ---------------------------------------------------------------------------
// Causal flash attention. One CTA = 64 queries of one (b,h).
// Qs,Ks stored [d][m] (transposed), Vs [n][d], Ps [n][m]. Online softmax.
// ---------------------------------------------------------------------------
#define APAD 68
#define ASM_BYTES (4 * 64 * APAD * 4)   // 69632

__global__ __launch_bounds__(256)
void attn_kernel(const float* __restrict__ Qg, const float* __restrict__ Kg,
                 const float* __restrict__ Vg, float* __restrict__ Og)
{
    extern __shared__ __align__(16) float smbuf[];
    float* Qs = smbuf;                  // [64][APAD]  (d, m)
    float* Ks = smbuf + 64 * APAD;      // [64][APAD]  (d, n)
    float* Vs = smbuf + 2 * 64 * APAD;  // [64][APAD]  (n, d)
    float* Ps = smbuf + 3 * 64 * APAD;  // [64][APAD]  (n, m)

    const int tid = threadIdx.x;
    const int tx = tid & 15;
    const int ty = tid >> 4;
    const int qb = blockIdx.x;
    const int bh = blockIdx.y;
    const int b  = bh >> 4;
    const int h  = bh & 15;
    const size_t base = (size_t)b * S_ * DM + (size_t)h * DK;
    const float scale = 0.125f;         // 1/sqrt(64)

    // load Q tile transposed: Qs[d][m]
#pragma unroll
    for (int i4 = 0; i4 < 4; i4++) {
        int e  = tid + i4 * 256;
        int r  = e >> 4;
        int d4 = (e & 15) << 2;
        float4 g = *(const float4*)&Qg[base + (size_t)(qb * 64 + r) * DM + d4];
        Qs[(d4 + 0) * APAD + r] = g.x;
        Qs[(d4 + 1) * APAD + r] = g.y;
        Qs[(d4 + 2) * APAD + r] = g.z;
        Qs[(d4 + 3) * APAD + r] = g.w;
    }

    float o[4][4];
    float mrow[4], lrow[4];
#pragma unroll
    for (int i = 0; i < 4; i++) {
        mrow[i] = -1e30f;
        lrow[i] = 0.f;
#pragma unroll
        for (int j = 0; j < 4; j++) o[i][j] = 0.f;
    }

    for (int kb = 0; kb <= qb; kb++) {
        __syncthreads();

        // load K transposed, V direct
#pragma unroll
        for (int i4 = 0; i4 < 4; i4++) {
            int e  = tid + i4 * 256;
            int r  = e >> 4;
            int d4 = (e & 15) << 2;
            size_t goff = base + (size_t)(kb * 64 + r) * DM + d4;
            float4 g = *(const float4*)&Kg[goff];
            Ks[(d4 + 0) * APAD + r] = g.x;
            Ks[(d4 + 1) * APAD + r] = g.y;
            Ks[(d4 + 2) * APAD + r] = g.z;
            Ks[(d4 + 3) * APAD + r] = g.w;
            float4 v = *(const float4*)&Vg[goff];
            *(float4*)&Vs[r * APAD + d4] = v;
        }
        __syncthreads();

        // scores
        float s[4][4];
#pragma unroll
        for (int i = 0; i < 4; i++)
#pragma unroll
            for (int j = 0; j < 4; j++) s[i][j] = 0.f;

#pragma unroll
        for (int d = 0; d < 64; d++) {
            float4 qv = *(float4*)&Qs[d * APAD + ty * 4];
            float4 kv = *(float4*)&Ks[d * APAD + tx * 4];
            float qa[4] = {qv.x, qv.y, qv.z, qv.w};
            float ka[4] = {kv.x, kv.y, kv.z, kv.w};
#pragma unroll
            for (int i = 0; i < 4; i++)
#pragma unroll
                for (int j = 0; j < 4; j++)
                    s[i][j] = fmaf(qa[i], ka[j], s[i][j]);
        }

        // scale + causal mask using GLOBAL indices
#pragma unroll
        for (int i = 0; i < 4; i++) {
            int gq = qb * 64 + ty * 4 + i;
#pragma unroll
            for (int j = 0; j < 4; j++) {
                int gk = kb * 64 + tx * 4 + j;
                s[i][j] = (gk > gq) ? -1e30f : s[i][j] * scale;
            }
        }

        // online softmax update per row
#pragma unroll
        for (int i = 0; i < 4; i++) {
            float rmax = fmaxf(fmaxf(s[i][0], s[i][1]), fmaxf(s[i][2], s[i][3]));
#pragma unroll
            for (int msk = 1; msk < 16; msk <<= 1)
                rmax = fmaxf(rmax, __shfl_xor_sync(0xffffffffu, rmax, msk));
            float mnew = fmaxf(mrow[i], rmax);
            float rsum = 0.f;
#pragma unroll
            for (int j = 0; j < 4; j++) {
                s[i][j] = expf(s[i][j] - mnew);
                rsum += s[i][j];
            }
#pragma unroll
            for (int msk = 1; msk < 16; msk <<= 1)
                rsum += __shfl_xor_sync(0xffffffffu, rsum, msk);
            float alpha = expf(mrow[i] - mnew);
            lrow[i] = lrow[i] * alpha + rsum;
            mrow[i] = mnew;
#pragma unroll
            for (int j = 0; j < 4; j++) o[i][j] *= alpha;
        }

        // write P transposed: Ps[n][m]
#pragma unroll
        for (int i = 0; i < 4; i++)
#pragma unroll
            for (int j = 0; j < 4; j++)
                Ps[(tx * 4 + j) * APAD + ty * 4 + i] = s[i][j];
        __syncthreads();

        // o += P @ V
#pragma unroll
        for (int n = 0; n < 64; n++) {
            float4 pv = *(float4*)&Ps[n * APAD + ty * 4];
            float4 vv = *(float4*)&Vs[n * APAD + tx * 4];
            float pa[4] = {pv.x, pv.y, pv.z, pv.w};
            float va[4] = {vv.x, vv.y, vv.z, vv.w};
#pragma unroll
            for (int i = 0; i < 4; i++)
#pragma unroll
                for (int j = 0; j < 4; j++)
                    o[i][j] = fmaf(pa[i], va[j], o[i][j]);
        }
    }

    // epilogue
#pragma unroll
    for (int i = 0; i < 4; i++) {
        float inv = 1.0f / lrow[i];
        float* op = Og + base + (size_t)(qb * 64 + ty * 4 + i) * DM + tx * 4;
        *(float4*)op = make_float4(o[i][0] * inv, o[i][1] * inv,
                                   o[i][2] * inv, o[i][3] * inv);
    }
}

// ---------------------------------------------------------------------------
extern "C" void kernel_launch(void* const* d_in, const int* in_sizes, int n_in,
                              void* d_out, int out_size)
{
    // Identify inputs by size (x = 4,194,304; pos = 2,048; weights = 1,048,576).
    const float *x, *Wq, *Wk, *Wv, *Wo;
    const int* pos;
    if (in_sizes[0] == MTOT * DM) {            // setup_inputs dict order
        x   = (const float*)d_in[0];
        pos = (const int*)  d_in[1];
        Wq  = (const float*)d_in[2];
        Wk  = (const float*)d_in[3];
        Wv  = (const float*)d_in[4];
        Wo  = (const float*)d_in[5];
    } else {                                   // name-sorted order
        Wk  = (const float*)d_in[0];
        Wo  = (const float*)d_in[1];
        Wq  = (const float*)d_in[2];
        Wv  = (const float*)d_in[3];
        pos = (const int*)  d_in[4];
        x   = (const float*)d_in[5];
    }
    float* out = (float*)d_out;

    float *Q, *K, *V, *A;
    float2* cs;
    cudaGetSymbolAddress((void**)&Q, g_Q);
    cudaGetSymbolAddress((void**)&K, g_K);
    cudaGetSymbolAddress((void**)&V, g_V);
    cudaGetSymbolAddress((void**)&A, g_A);
    cudaGetSymbolAddress((void**)&cs, g_cs);

    build_cs_kernel<<<(S_ * (DK/2) + 255) / 256, 256>>>(pos, cs);

    dim3 gg(DM / GBN, MTOT / GBM);   // (8, 32)

    sgemm_xwt<true ><<<gg, 256>>>(x, Wq, Q, cs, MTOT, DM, DM);
    sgemm_xwt<true ><<<gg, 256>>>(x, Wk, K, cs, MTOT, DM, DM);
    sgemm_xwt<false><<<gg, 256>>>(x, Wv, V, nullptr, MTOT, DM, DM);

    cudaFuncSetAttribute(attn_kernel, cudaFuncAttributeMaxDynamicSharedMemorySize,
                         ASM_BYTES);
    attn_kernel<<<dim3(S_ / 64, B_ * NH), 256, ASM_BYTES>>>(Q, K, V, A);

    sgemm_xwt<false><<<gg, 256>>>(A, Wo, out, nullptr, MTOT, DM, DM);
}

// round 5
// speedup vs baseline: 1.9091x; 1.5011x over previous
#include <cuda_runtime.h>
#include <cuda_bf16.h>
#include <math.h>
#include <stdint.h>

#define DM 1024
#define NH 16
#define DK 64
#define B_ 2
#define S_ 2048
#define MTOT (B_*S_)   // 4096

// ---------------- scratch (device globals: allocation-free) ----------------
__device__ float g_Q[MTOT*DM];
__device__ float g_K[MTOT*DM];
__device__ float g_V[MTOT*DM];
__device__ float g_A[MTOT*DM];
__device__ float2 g_cs[S_ * (DK/2)];
__device__ __nv_bfloat16 g_xhi[MTOT*DM];
__device__ __nv_bfloat16 g_xlo[MTOT*DM];
__device__ __nv_bfloat16 g_whi[4][DM*DM];
__device__ __nv_bfloat16 g_wlo[4][DM*DM];

// ---------------- family-portable PTX helpers (sm_80-era; OK on sm_103) ----
__device__ __forceinline__ uint32_t smem_u32(const void* p) {
    uint32_t a;
    asm("{ .reg .u64 t; cvta.to.shared.u64 t, %1; cvt.u32.u64 %0, t; }"
        : "=r"(a) : "l"(p));
    return a;
}
#define CP16(saddr, gptr) \
    asm volatile("cp.async.cg.shared.global [%0], [%1], 16;" :: "r"(saddr), "l"(gptr))
#define CPCOMMIT() asm volatile("cp.async.commit_group;" ::: "memory")
#define CPWAIT0()  asm volatile("cp.async.wait_group 0;" ::: "memory")
#define CPWAIT1()  asm volatile("cp.async.wait_group 1;" ::: "memory")
#define LDSM4(r, addr) \
    asm volatile("ldmatrix.sync.aligned.m8n8.x4.shared.b16 {%0,%1,%2,%3}, [%4];" \
        : "=r"((r)[0]), "=r"((r)[1]), "=r"((r)[2]), "=r"((r)[3]) : "r"(addr))
#define MMA_BF16(d, a, b) \
    asm volatile("mma.sync.aligned.m16n8k16.row.col.f32.bf16.bf16.f32 " \
        "{%0,%1,%2,%3},{%4,%5,%6,%7},{%8,%9},{%0,%1,%2,%3};" \
        : "+f"((d)[0]), "+f"((d)[1]), "+f"((d)[2]), "+f"((d)[3]) \
        : "r"((a)[0]), "r"((a)[1]), "r"((a)[2]), "r"((a)[3]), \
          "r"((b)[0]), "r"((b)[1]))

// ---------------------------------------------------------------------------
// cos/sin table (fp64 trig of the fp32 angle; fast-math immune)
// ---------------------------------------------------------------------------
__global__ void build_cs_kernel(const int* __restrict__ pos, float2* __restrict__ cs)
{
    int idx = blockIdx.x * blockDim.x + threadIdx.x;
    if (idx >= S_ * (DK/2)) return;
    int s = idx >> 5, p = idx & 31;
    float posf = (float)pos[s];
    double e   = (double)(2 * p) / (double)DK;
    float inv  = (float)exp(-e * log(10000.0));
    float ang  = posf * inv;
    cs[idx] = make_float2((float)cos((double)ang), (float)sin((double)ang));
}

// ---------------------------------------------------------------------------
// fp32 -> (bf16 hi, bf16 lo) split. 8 elements per thread.
// ---------------------------------------------------------------------------
__global__ void split_kernel(const float* __restrict__ src,
                             __nv_bfloat16* __restrict__ hi,
                             __nv_bfloat16* __restrict__ lo, int n)
{
    int i = (blockIdx.x * blockDim.x + threadIdx.x) * 8;
    if (i >= n) return;
    float4 a = *(const float4*)(src + i);
    float4 b = *(const float4*)(src + i + 4);
    float v[8] = {a.x, a.y, a.z, a.w, b.x, b.y, b.z, b.w};
    unsigned short hs[8], ls[8];
#pragma unroll
    for (int j = 0; j < 8; j++) {
        __nv_bfloat16 h = __float2bfloat16(v[j]);
        __nv_bfloat16 l = __float2bfloat16(v[j] - __bfloat162float(h));
        hs[j] = __bfloat16_as_ushort(h);
        ls[j] = __bfloat16_as_ushort(l);
    }
    uint4 hp, lp;
    hp.x = hs[0] | ((uint32_t)hs[1] << 16); hp.y = hs[2] | ((uint32_t)hs[3] << 16);
    hp.z = hs[4] | ((uint32_t)hs[5] << 16); hp.w = hs[6] | ((uint32_t)hs[7] << 16);
    lp.x = ls[0] | ((uint32_t)ls[1] << 16); lp.y = ls[2] | ((uint32_t)ls[3] << 16);
    lp.z = ls[4] | ((uint32_t)ls[5] << 16); lp.w = ls[6] | ((uint32_t)ls[7] << 16);
    *(uint4*)((unsigned short*)hi + i) = hp;
    *(uint4*)((unsigned short*)lo + i) = lp;
}

// ---------------------------------------------------------------------------
// Split-bf16 tensor-core GEMM: Y[4096,1024] = X @ W^T.
// 128x128 CTA tile, BK=32, 8 warps (4m x 2n), warp tile 32x64.
// mma.sync m16n8k16 bf16, 3 products per k16 (hi*hi + hi*lo + lo*hi).
// cp.async 2-stage pipeline. Optional fused RoPE epilogue.
// ---------------------------------------------------------------------------
#define BKK 32
#define NKB (DM / BKK)                 // 32
#define SROW 40                        // bf16 per smem row (32 + 8 pad)
#define TILE_BYTES (128 * SROW * 2)    // 10240
#define STAGE_BYTES (4 * TILE_BYTES)   // 40960: Ahi,Alo,Bhi,Blo
#define GSMEM (2 * STAGE_BYTES)        // 81920

template<bool ROPE>
__global__ __launch_bounds__(256)
void gemm_mma(const __nv_bfloat16* __restrict__ Ahi, const __nv_bfloat16* __restrict__ Alo,
              const __nv_bfloat16* __restrict__ Bhi, const __nv_bfloat16* __restrict__ Blo,
              float* __restrict__ Y, const float2* __restrict__ cs)
{
    extern __shared__ char sm[];
    const uint32_t sb = smem_u32(sm);

    const int tid  = threadIdx.x;
    const int lane = tid & 31;
    const int wid  = tid >> 5;
    const int wm   = (wid & 3) * 32;
    const int wn   = (wid >> 2) * 64;
    const int m0   = blockIdx.y * 128;
    const int n0   = blockIdx.x * 128;

    const __nv_bfloat16* gt[4] = {Ahi, Alo, Bhi, Blo};
    const int rb[4] = {m0, m0, n0, n0};

    // per-thread load coords: 512 16B-chunks per tile, 2 per thread per tile
    const int r0c = tid >> 2, c0 = (tid & 3) * 8;          // chunk 0: row, bf16 col
    const int r1c = (tid + 256) >> 2, c1 = c0;             // chunk 1 (same c4 pattern)

#define LOAD_STAGE(sidx, kb) do {                                             \
    uint32_t sdst = sb + (sidx) * STAGE_BYTES;                                \
    int kofs = (kb) * BKK;                                                    \
    _Pragma("unroll")                                                         \
    for (int t = 0; t < 4; t++) {                                             \
        CP16(sdst + t * TILE_BYTES + (r0c * SROW + c0) * 2,                   \
             gt[t] + (size_t)(rb[t] + r0c) * DM + kofs + c0);                 \
        CP16(sdst + t * TILE_BYTES + (r1c * SROW + c1) * 2,                   \
             gt[t] + (size_t)(rb[t] + r1c) * DM + kofs + c1);                 \
    }                                                                         \
} while (0)

    float acc[2][8][4];
#pragma unroll
    for (int i = 0; i < 2; i++)
#pragma unroll
        for (int j = 0; j < 8; j++)
#pragma unroll
            for (int q = 0; q < 4; q++) acc[i][j][q] = 0.f;

    LOAD_STAGE(0, 0);
    CPCOMMIT();

    for (int kb = 0; kb < NKB; kb++) {
        if (kb + 1 < NKB) { LOAD_STAGE((kb + 1) & 1, kb + 1); CPCOMMIT(); CPWAIT1(); }
        else              { CPWAIT0(); }
        __syncthreads();

        const uint32_t sst = sb + (kb & 1) * STAGE_BYTES;
#pragma unroll
        for (int kk = 0; kk < 2; kk++) {
            uint32_t a_hi[2][4], a_lo[2][4], b_hi[4][4], b_lo[4][4];
            const int ar = wm + (lane & 15);
            const int ac = kk * 16 + (lane >> 4) * 8;
#pragma unroll
            for (int i = 0; i < 2; i++) {
                uint32_t ad = sst + (((ar + i * 16) * SROW + ac) << 1);
                LDSM4(a_hi[i], ad);
                LDSM4(a_lo[i], ad + TILE_BYTES);
            }
            const int br = wn + ((lane >> 4) << 3) + (lane & 7);
            const int bc = kk * 16 + ((lane >> 3) & 1) * 8;
#pragma unroll
            for (int j = 0; j < 4; j++) {
                uint32_t bd = sst + 2 * TILE_BYTES + (((br + j * 16) * SROW + bc) << 1);
                LDSM4(b_hi[j], bd);
                LDSM4(b_lo[j], bd + TILE_BYTES);
            }
#pragma unroll
            for (int i = 0; i < 2; i++)
#pragma unroll
                for (int j = 0; j < 8; j++) {
                    const uint32_t* bh = &b_hi[j >> 1][(j & 1) * 2];
                    const uint32_t* bl = &b_lo[j >> 1][(j & 1) * 2];
                    MMA_BF16(acc[i][j], a_hi[i], bh);
                    MMA_BF16(acc[i][j], a_hi[i], bl);
                    MMA_BF16(acc[i][j], a_lo[i], bh);
                }
        }
        __syncthreads();
    }
#undef LOAD_STAGE

    // epilogue (+ optional fused RoPE); thread owns adjacent even/odd cols
#pragma unroll
    for (int i = 0; i < 2; i++)
#pragma unroll
        for (int j = 0; j < 8; j++) {
            const int col = n0 + wn + j * 8 + (lane & 3) * 2;
#pragma unroll
            for (int h = 0; h < 2; h++) {
                const int row = m0 + wm + i * 16 + (lane >> 2) + h * 8;
                float v0 = acc[i][j][h * 2], v1 = acc[i][j][h * 2 + 1];
                if (ROPE) {
                    int s = row & (S_ - 1);
                    float2 cp = cs[s * 32 + ((col & (DK - 1)) >> 1)];
                    float o0 = v0 * cp.x - v1 * cp.y;
                    float o1 = v0 * cp.y + v1 * cp.x;
                    v0 = o0; v1 = o1;
                }
                *(float2*)(Y + (size_t)row * DM + col) = make_float2(v0, v1);
            }
        }
}

// ---------------------------------------------------------------------------
// Causal flash attention (unchanged; passing at round 3). One CTA = 64 queries.
// ---------------------------------------------------------------------------
#define APAD 68
#define ASM_BYTES (4 * 64 * APAD * 4)

__global__ __launch_bounds__(256)
void attn_kernel(const float* __restrict__ Qg, const float* __restrict__ Kg,
                 const float* __restrict__ Vg, float* __restrict__ Og)
{
    extern __shared__ __align__(16) float smbuf[];
    float* Qs = smbuf;
    float* Ks = smbuf + 64 * APAD;
    float* Vs = smbuf + 2 * 64 * APAD;
    float* Ps = smbuf + 3 * 64 * APAD;

    const int tid = threadIdx.x;
    const int tx = tid & 15;
    const int ty = tid >> 4;
    const int qb = blockIdx.x;
    const int bh = blockIdx.y;
    const int b  = bh >> 4;
    const int h  = bh & 15;
    const size_t base = (size_t)b * S_ * DM + (size_t)h * DK;
    const float scale = 0.125f;

#pragma unroll
    for (int i4 = 0; i4 < 4; i4++) {
        int e  = tid + i4 * 256;
        int r  = e >> 4;
        int d4 = (e & 15) << 2;
        float4 g = *(const float4*)&Qg[base + (size_t)(qb * 64 + r) * DM + d4];
        Qs[(d4 + 0) * APAD + r] = g.x;
        Qs[(d4 + 1) * APAD + r] = g.y;
        Qs[(d4 + 2) * APAD + r] = g.z;
        Qs[(d4 + 3) * APAD + r] = g.w;
    }

    float o[4][4];
    float mrow[4], lrow[4];
#pragma unroll
    for (int i = 0; i < 4; i++) {
        mrow[i] = -1e30f; lrow[i] = 0.f;
#pragma unroll
        for (int j = 0; j < 4; j++) o[i][j] = 0.f;
    }

    for (int kb = 0; kb <= qb; kb++) {
        __syncthreads();
#pragma unroll
        for (int i4 = 0; i4 < 4; i4++) {
            int e  = tid + i4 * 256;
            int r  = e >> 4;
            int d4 = (e & 15) << 2;
            size_t goff = base + (size_t)(kb * 64 + r) * DM + d4;
            float4 g = *(const float4*)&Kg[goff];
            Ks[(d4 + 0) * APAD + r] = g.x;
            Ks[(d4 + 1) * APAD + r] = g.y;
            Ks[(d4 + 2) * APAD + r] = g.z;
            Ks[(d4 + 3) * APAD + r] = g.w;
            float4 v = *(const float4*)&Vg[goff];
            *(float4*)&Vs[r * APAD + d4] = v;
        }
        __syncthreads();

        float s[4][4];
#pragma unroll
        for (int i = 0; i < 4; i++)
#pragma unroll
            for (int j = 0; j < 4; j++) s[i][j] = 0.f;

#pragma unroll
        for (int d = 0; d < 64; d++) {
            float4 qv = *(float4*)&Qs[d * APAD + ty * 4];
            float4 kv = *(float4*)&Ks[d * APAD + tx * 4];
            float qa[4] = {qv.x, qv.y, qv.z, qv.w};
            float ka[4] = {kv.x, kv.y, kv.z, kv.w};
#pragma unroll
            for (int i = 0; i < 4; i++)
#pragma unroll
                for (int j = 0; j < 4; j++)
                    s[i][j] = fmaf(qa[i], ka[j], s[i][j]);
        }

#pragma unroll
        for (int i = 0; i < 4; i++) {
            int gq = qb * 64 + ty * 4 + i;
#pragma unroll
            for (int j = 0; j < 4; j++) {
                int gk = kb * 64 + tx * 4 + j;
                s[i][j] = (gk > gq) ? -1e30f : s[i][j] * scale;
            }
        }

#pragma unroll
        for (int i = 0; i < 4; i++) {
            float rmax = fmaxf(fmaxf(s[i][0], s[i][1]), fmaxf(s[i][2], s[i][3]));
#pragma unroll
            for (int msk = 1; msk < 16; msk <<= 1)
                rmax = fmaxf(rmax, __shfl_xor_sync(0xffffffffu, rmax, msk));
            float mnew = fmaxf(mrow[i], rmax);
            float rsum = 0.f;
#pragma unroll
            for (int j = 0; j < 4; j++) {
                s[i][j] = expf(s[i][j] - mnew);
                rsum += s[i][j];
            }
#pragma unroll
            for (int msk = 1; msk < 16; msk <<= 1)
                rsum += __shfl_xor_sync(0xffffffffu, rsum, msk);
            float alpha = expf(mrow[i] - mnew);
            lrow[i] = lrow[i] * alpha + rsum;
            mrow[i] = mnew;
#pragma unroll
            for (int j = 0; j < 4; j++) o[i][j] *= alpha;
        }

#pragma unroll
        for (int i = 0; i < 4; i++)
#pragma unroll
            for (int j = 0; j < 4; j++)
                Ps[(tx * 4 + j) * APAD + ty * 4 + i] = s[i][j];
        __syncthreads();

#pragma unroll
        for (int n = 0; n < 64; n++) {
            float4 pv = *(float4*)&Ps[n * APAD + ty * 4];
            float4 vv = *(float4*)&Vs[n * APAD + tx * 4];
            float pa[4] = {pv.x, pv.y, pv.z, pv.w};
            float va[4] = {vv.x, vv.y, vv.z, vv.w};
#pragma unroll
            for (int i = 0; i < 4; i++)
#pragma unroll
                for (int j = 0; j < 4; j++)
                    o[i][j] = fmaf(pa[i], va[j], o[i][j]);
        }
    }

#pragma unroll
    for (int i = 0; i < 4; i++) {
        float inv = 1.0f / lrow[i];
        float* op = Og + base + (size_t)(qb * 64 + ty * 4 + i) * DM + tx * 4;
        *(float4*)op = make_float4(o[i][0] * inv, o[i][1] * inv,
                                   o[i][2] * inv, o[i][3] * inv);
    }
}

// ---------------------------------------------------------------------------
extern "C" void kernel_launch(void* const* d_in, const int* in_sizes, int n_in,
                              void* d_out, int out_size)
{
    const float *x, *Wq, *Wk, *Wv, *Wo;
    const int* pos;
    if (in_sizes[0] == MTOT * DM) {            // setup_inputs dict order
        x   = (const float*)d_in[0];
        pos = (const int*)  d_in[1];
        Wq  = (const float*)d_in[2];
        Wk  = (const float*)d_in[3];
        Wv  = (const float*)d_in[4];
        Wo  = (const float*)d_in[5];
    } else {                                   // name-sorted order
        Wk  = (const float*)d_in[0];
        Wo  = (const float*)d_in[1];
        Wq  = (const float*)d_in[2];
        Wv  = (const float*)d_in[3];
        pos = (const int*)  d_in[4];
        x   = (const float*)d_in[5];
    }
    float* out = (float*)d_out;

    float *Q, *K, *V, *A;
    float2* cs;
    __nv_bfloat16 *xhi, *xlo, *whi, *wlo;
    cudaGetSymbolAddress((void**)&Q, g_Q);
    cudaGetSymbolAddress((void**)&K, g_K);
    cudaGetSymbolAddress((void**)&V, g_V);
    cudaGetSymbolAddress((void**)&A, g_A);
    cudaGetSymbolAddress((void**)&cs, g_cs);
    cudaGetSymbolAddress((void**)&xhi, g_xhi);
    cudaGetSymbolAddress((void**)&xlo, g_xlo);
    cudaGetSymbolAddress((void**)&whi, g_whi);
    cudaGetSymbolAddress((void**)&wlo, g_wlo);

    build_cs_kernel<<<(S_ * (DK/2) + 255) / 256, 256>>>(pos, cs);

    const int NX = MTOT * DM, NW = DM * DM;
    split_kernel<<<NX / 8 / 256, 256>>>(x,  xhi, xlo, NX);
    split_kernel<<<NW / 8 / 256, 256>>>(Wq, whi + 0 * (size_t)NW, wlo + 0 * (size_t)NW, NW);
    split_kernel<<<NW / 8 / 256, 256>>>(Wk, whi + 1 * (size_t)NW, wlo + 1 * (size_t)NW, NW);
    split_kernel<<<NW / 8 / 256, 256>>>(Wv, whi + 2 * (size_t)NW, wlo + 2 * (size_t)NW, NW);
    split_kernel<<<NW / 8 / 256, 256>>>(Wo, whi + 3 * (size_t)NW, wlo + 3 * (size_t)NW, NW);

    cudaFuncSetAttribute(gemm_mma<true>,  cudaFuncAttributeMaxDynamicSharedMemorySize, GSMEM);
    cudaFuncSetAttribute(gemm_mma<false>, cudaFuncAttributeMaxDynamicSharedMemorySize, GSMEM);

    dim3 gg(DM / 128, MTOT / 128);   // (8, 32)
    gemm_mma<true ><<<gg, 256, GSMEM>>>(xhi, xlo, whi + 0 * (size_t)NW, wlo + 0 * (size_t)NW, Q, cs);
    gemm_mma<true ><<<gg, 256, GSMEM>>>(xhi, xlo, whi + 1 * (size_t)NW, wlo + 1 * (size_t)NW, K, cs);
    gemm_mma<false><<<gg, 256, GSMEM>>>(xhi, xlo, whi + 2 * (size_t)NW, wlo + 2 * (size_t)NW, V, nullptr);

    cudaFuncSetAttribute(attn_kernel, cudaFuncAttributeMaxDynamicSharedMemorySize, ASM_BYTES);
    attn_kernel<<<dim3(S_ / 64, B_ * NH), 256, ASM_BYTES>>>(Q, K, V, A);

    split_kernel<<<NX / 8 / 256, 256>>>(A, xhi, xlo, NX);
    gemm_mma<false><<<gg, 256, GSMEM>>>(xhi, xlo, whi + 3 * (size_t)NW, wlo + 3 * (size_t)NW, out, nullptr);
}

// round 6
// speedup vs baseline: 3.1698x; 1.6604x over previous
#include <cuda_runtime.h>
#include <cuda_bf16.h>
#include <math.h>
#include <stdint.h>

#define DM 1024
#define NH 16
#define DK 64
#define B_ 2
#define S_ 2048
#define MTOT (B_*S_)   // 4096

// ---------------- scratch (device globals: allocation-free) ----------------
__device__ float2 g_cs[S_ * (DK/2)];
__device__ __nv_bfloat16 g_xhi[MTOT*DM];
__device__ __nv_bfloat16 g_xlo[MTOT*DM];
__device__ __nv_bfloat16 g_whi[4][DM*DM];
__device__ __nv_bfloat16 g_wlo[4][DM*DM];
__device__ __nv_bfloat16 g_qhi[MTOT*DM];
__device__ __nv_bfloat16 g_qlo[MTOT*DM];
__device__ __nv_bfloat16 g_khi[MTOT*DM];
__device__ __nv_bfloat16 g_klo[MTOT*DM];
__device__ __nv_bfloat16 g_vhi[MTOT*DM];
__device__ __nv_bfloat16 g_vlo[MTOT*DM];

// ---------------- family-portable PTX helpers ----------------
__device__ __forceinline__ uint32_t smem_u32(const void* p) {
    uint32_t a;
    asm("{ .reg .u64 t; cvta.to.shared.u64 t, %1; cvt.u32.u64 %0, t; }"
        : "=r"(a) : "l"(p));
    return a;
}
#define CP16(saddr, gptr) \
    asm volatile("cp.async.cg.shared.global [%0], [%1], 16;" :: "r"(saddr), "l"(gptr))
#define CPCOMMIT() asm volatile("cp.async.commit_group;" ::: "memory")
#define CPWAIT0()  asm volatile("cp.async.wait_group 0;" ::: "memory")
#define CPWAIT1()  asm volatile("cp.async.wait_group 1;" ::: "memory")
#define LDSM4(r, addr) \
    asm volatile("ldmatrix.sync.aligned.m8n8.x4.shared.b16 {%0,%1,%2,%3}, [%4];" \
        : "=r"((r)[0]), "=r"((r)[1]), "=r"((r)[2]), "=r"((r)[3]) : "r"(addr))
#define LDSM4T(r, addr) \
    asm volatile("ldmatrix.sync.aligned.m8n8.x4.trans.shared.b16 {%0,%1,%2,%3}, [%4];" \
        : "=r"((r)[0]), "=r"((r)[1]), "=r"((r)[2]), "=r"((r)[3]) : "r"(addr))
#define MMA_BF16(d, a, b) \
    asm volatile("mma.sync.aligned.m16n8k16.row.col.f32.bf16.bf16.f32 " \
        "{%0,%1,%2,%3},{%4,%5,%6,%7},{%8,%9},{%0,%1,%2,%3};" \
        : "+f"((d)[0]), "+f"((d)[1]), "+f"((d)[2]), "+f"((d)[3]) \
        : "r"((a)[0]), "r"((a)[1]), "r"((a)[2]), "r"((a)[3]), \
          "r"((b)[0]), "r"((b)[1]))

__device__ __forceinline__ float ex2f(float x) {
    float y; asm("ex2.approx.ftz.f32 %0, %1;" : "=f"(y) : "f"(x)); return y;
}
__device__ __forceinline__ void split2(float v0, float v1, uint32_t& hi, uint32_t& lo) {
    __nv_bfloat16 h0 = __float2bfloat16(v0), h1 = __float2bfloat16(v1);
    __nv_bfloat16 l0 = __float2bfloat16(v0 - __bfloat162float(h0));
    __nv_bfloat16 l1 = __float2bfloat16(v1 - __bfloat162float(h1));
    hi = ((uint32_t)__bfloat16_as_ushort(h1) << 16) | __bfloat16_as_ushort(h0);
    lo = ((uint32_t)__bfloat16_as_ushort(l1) << 16) | __bfloat16_as_ushort(l0);
}

// ---------------------------------------------------------------------------
// cos/sin table
// ---------------------------------------------------------------------------
__global__ void build_cs_kernel(const int* __restrict__ pos, float2* __restrict__ cs)
{
    int idx = blockIdx.x * blockDim.x + threadIdx.x;
    if (idx >= S_ * (DK/2)) return;
    int s = idx >> 5, p = idx & 31;
    float posf = (float)pos[s];
    double e   = (double)(2 * p) / (double)DK;
    float inv  = (float)exp(-e * log(10000.0));
    float ang  = posf * inv;
    cs[idx] = make_float2((float)cos((double)ang), (float)sin((double)ang));
}

// ---------------------------------------------------------------------------
// fp32 -> (bf16 hi, bf16 lo) split
// ---------------------------------------------------------------------------
__global__ void split_kernel(const float* __restrict__ src,
                             __nv_bfloat16* __restrict__ hi,
                             __nv_bfloat16* __restrict__ lo, int n)
{
    int i = (blockIdx.x * blockDim.x + threadIdx.x) * 8;
    if (i >= n) return;
    float4 a = *(const float4*)(src + i);
    float4 b = *(const float4*)(src + i + 4);
    float v[8] = {a.x, a.y, a.z, a.w, b.x, b.y, b.z, b.w};
    uint4 hp, lp;
    uint32_t* hw = (uint32_t*)&hp;
    uint32_t* lw = (uint32_t*)&lp;
#pragma unroll
    for (int j = 0; j < 4; j++) split2(v[2*j], v[2*j+1], hw[j], lw[j]);
    *(uint4*)((unsigned short*)hi + i) = hp;
    *(uint4*)((unsigned short*)lo + i) = lp;
}

// ---------------------------------------------------------------------------
// Split-bf16 tensor-core GEMM: Y = X @ W^T. 128x128 tile, BK=32, 8 warps.
// MODE: 0 = fp32 out, 1 = RoPE + bf16 hi/lo out, 2 = bf16 hi/lo out
// ---------------------------------------------------------------------------
#define BKK 32
#define NKB (DM / BKK)
#define SROW 40
#define TILE_BYTES (128 * SROW * 2)
#define STAGE_BYTES (4 * TILE_BYTES)
#define GSMEM (2 * STAGE_BYTES)

template<int MODE>
__global__ __launch_bounds__(256)
void gemm_mma(const __nv_bfloat16* __restrict__ Ahi, const __nv_bfloat16* __restrict__ Alo,
              const __nv_bfloat16* __restrict__ Bhi, const __nv_bfloat16* __restrict__ Blo,
              float* __restrict__ Y, __nv_bfloat16* __restrict__ Yhi,
              __nv_bfloat16* __restrict__ Ylo, const float2* __restrict__ cs)
{
    extern __shared__ char sm[];
    const uint32_t sb = smem_u32(sm);

    const int tid  = threadIdx.x;
    const int lane = tid & 31;
    const int wid  = tid >> 5;
    const int wm   = (wid & 3) * 32;
    const int wn   = (wid >> 2) * 64;
    const int m0   = blockIdx.y * 128;
    const int n0   = blockIdx.x * 128;

    const __nv_bfloat16* gt[4] = {Ahi, Alo, Bhi, Blo};
    const int rb[4] = {m0, m0, n0, n0};

    const int r0c = tid >> 2, c0 = (tid & 3) * 8;
    const int r1c = (tid + 256) >> 2, c1 = c0;

#define LOAD_STAGE(sidx, kb) do {                                             \
    uint32_t sdst = sb + (sidx) * STAGE_BYTES;                                \
    int kofs = (kb) * BKK;                                                    \
    _Pragma("unroll")                                                         \
    for (int t = 0; t < 4; t++) {                                             \
        CP16(sdst + t * TILE_BYTES + (r0c * SROW + c0) * 2,                   \
             gt[t] + (size_t)(rb[t] + r0c) * DM + kofs + c0);                 \
        CP16(sdst + t * TILE_BYTES + (r1c * SROW + c1) * 2,                   \
             gt[t] + (size_t)(rb[t] + r1c) * DM + kofs + c1);                 \
    }                                                                         \
} while (0)

    float acc[2][8][4];
#pragma unroll
    for (int i = 0; i < 2; i++)
#pragma unroll
        for (int j = 0; j < 8; j++)
#pragma unroll
            for (int q = 0; q < 4; q++) acc[i][j][q] = 0.f;

    LOAD_STAGE(0, 0);
    CPCOMMIT();

    for (int kb = 0; kb < NKB; kb++) {
        if (kb + 1 < NKB) { LOAD_STAGE((kb + 1) & 1, kb + 1); CPCOMMIT(); CPWAIT1(); }
        else              { CPWAIT0(); }
        __syncthreads();

        const uint32_t sst = sb + (kb & 1) * STAGE_BYTES;
#pragma unroll
        for (int kk = 0; kk < 2; kk++) {
            uint32_t a_hi[2][4], a_lo[2][4], b_hi[4][4], b_lo[4][4];
            const int ar = wm + (lane & 15);
            const int ac = kk * 16 + (lane >> 4) * 8;
#pragma unroll
            for (int i = 0; i < 2; i++) {
                uint32_t ad = sst + (((ar + i * 16) * SROW + ac) << 1);
                LDSM4(a_hi[i], ad);
                LDSM4(a_lo[i], ad + TILE_BYTES);
            }
            const int br = wn + ((lane >> 4) << 3) + (lane & 7);
            const int bc = kk * 16 + ((lane >> 3) & 1) * 8;
#pragma unroll
            for (int j = 0; j < 4; j++) {
                uint32_t bd = sst + 2 * TILE_BYTES + (((br + j * 16) * SROW + bc) << 1);
                LDSM4(b_hi[j], bd);
                LDSM4(b_lo[j], bd + TILE_BYTES);
            }
#pragma unroll
            for (int i = 0; i < 2; i++)
#pragma unroll
                for (int j = 0; j < 8; j++) {
                    const uint32_t* bh = &b_hi[j >> 1][(j & 1) * 2];
                    const uint32_t* bl = &b_lo[j >> 1][(j & 1) * 2];
                    MMA_BF16(acc[i][j], a_hi[i], bh);
                    MMA_BF16(acc[i][j], a_hi[i], bl);
                    MMA_BF16(acc[i][j], a_lo[i], bh);
                }
        }
        __syncthreads();
    }
#undef LOAD_STAGE

#pragma unroll
    for (int i = 0; i < 2; i++)
#pragma unroll
        for (int j = 0; j < 8; j++) {
            const int col = n0 + wn + j * 8 + (lane & 3) * 2;
#pragma unroll
            for (int h = 0; h < 2; h++) {
                const int row = m0 + wm + i * 16 + (lane >> 2) + h * 8;
                float v0 = acc[i][j][h * 2], v1 = acc[i][j][h * 2 + 1];
                if (MODE == 1) {
                    int s = row & (S_ - 1);
                    float2 cp = cs[s * 32 + ((col & (DK - 1)) >> 1)];
                    float o0 = v0 * cp.x - v1 * cp.y;
                    float o1 = v0 * cp.y + v1 * cp.x;
                    v0 = o0; v1 = o1;
                }
                if (MODE == 0) {
                    *(float2*)(Y + (size_t)row * DM + col) = make_float2(v0, v1);
                } else {
                    uint32_t hp, lp;
                    split2(v0, v1, hp, lp);
                    *(uint32_t*)((unsigned short*)Yhi + (size_t)row * DM + col) = hp;
                    *(uint32_t*)((unsigned short*)Ylo + (size_t)row * DM + col) = lp;
                }
            }
        }
}

// ---------------------------------------------------------------------------
// Tensor-core causal flash attention, split bf16.
// CTA = 128 queries of one (b,h). 8 warps x 16 rows (full-row ownership).
// Keys in 64-blocks, 2-stage cp.async pipeline. S and PV each 3 split MMAs.
// ---------------------------------------------------------------------------
#define SP 72
#define QBB (128 * SP * 2)          // 18432 per Q array
#define KVB (64 * SP * 2)           // 9216 per K/V array
#define STG (4 * KVB)               // 36864 per stage
#define ATT_SMEM (2 * QBB + 2 * STG)  // 110592

__global__ __launch_bounds__(256)
void attn_mma(const __nv_bfloat16* __restrict__ Qhi, const __nv_bfloat16* __restrict__ Qlo,
              const __nv_bfloat16* __restrict__ Khi, const __nv_bfloat16* __restrict__ Klo,
              const __nv_bfloat16* __restrict__ Vhi, const __nv_bfloat16* __restrict__ Vlo,
              __nv_bfloat16* __restrict__ Ahi, __nv_bfloat16* __restrict__ Alo)
{
    extern __shared__ char sm[];
    const uint32_t sb = smem_u32(sm);
    const uint32_t sQh = sb, sQl = sb + QBB;
    const uint32_t sStage = sb + 2 * QBB;

    const int tid = threadIdx.x, lane = tid & 31, wid = tid >> 5;
    const int qb = 15 - blockIdx.x;        // heavy blocks first
    const int bh = blockIdx.y;
    const int b = bh >> 4, h = bh & 15;
    const int wm = wid * 16;
    const size_t rowbase = (size_t)b * S_;
    const int hoff = h * DK;

    // Q tile (128 rows) hi/lo
#pragma unroll
    for (int i = 0; i < 4; i++) {
        int id = tid + i * 256;
        int r = id >> 3, c = (id & 7) * 8;
        size_t g = (rowbase + qb * 128 + r) * DM + hoff + c;
        uint32_t so = (r * SP + c) * 2;
        CP16(sQh + so, Qhi + g);
        CP16(sQl + so, Qlo + g);
    }

#define LOAD_KV(sidx, kb_) do {                                               \
    uint32_t dst = sStage + (sidx) * STG;                                     \
    size_t krow0 = rowbase + (size_t)(kb_) * 64;                              \
    _Pragma("unroll")                                                         \
    for (int i = 0; i < 2; i++) {                                             \
        int id = tid + i * 256;                                               \
        int r = id >> 3, c = (id & 7) * 8;                                    \
        size_t g = (krow0 + r) * DM + hoff + c;                               \
        uint32_t so = (r * SP + c) * 2;                                       \
        CP16(dst + 0 * KVB + so, Khi + g);                                    \
        CP16(dst + 1 * KVB + so, Klo + g);                                    \
        CP16(dst + 2 * KVB + so, Vhi + g);                                    \
        CP16(dst + 3 * KVB + so, Vlo + g);                                    \
    }                                                                         \
} while (0)

    LOAD_KV(0, 0);
    CPCOMMIT();

    float m2[2] = {-1e30f, -1e30f}, l[2] = {0.f, 0.f};
    float oacc[8][4];
#pragma unroll
    for (int j = 0; j < 8; j++)
#pragma unroll
        for (int q = 0; q < 4; q++) oacc[j][q] = 0.f;

    // ldmatrix lane offsets (bytes)
    const uint32_t q_off  = ((uint32_t)(wm + (lane & 15)) * SP + (lane >> 4) * 8) * 2;
    const uint32_t k_loff = ((uint32_t)(((lane >> 4) << 3) + (lane & 7)) * SP
                             + ((lane >> 3) & 1) * 8) * 2;
    const uint32_t v_loff = ((uint32_t)(lane & 15) * SP + (lane >> 4) * 8) * 2;

    const float SC2 = 0.125f * 1.4426950408889634f;   // scale * log2(e)
    const int nkb = 2 * qb + 2;

    for (int kb = 0; kb < nkb; kb++) {
        if (kb + 1 < nkb) { LOAD_KV((kb + 1) & 1, kb + 1); CPCOMMIT(); CPWAIT1(); }
        else              { CPWAIT0(); }
        __syncthreads();

        const uint32_t sK = sStage + (kb & 1) * STG;
        const uint32_t sV = sK + 2 * KVB;

        // ---- S = Q K^T (3 split MMAs per step)
        float sacc[8][4];
#pragma unroll
        for (int j = 0; j < 8; j++)
#pragma unroll
            for (int q = 0; q < 4; q++) sacc[j][q] = 0.f;

#pragma unroll
        for (int kc = 0; kc < 4; kc++) {
            uint32_t a_h[4], a_l[4];
            LDSM4(a_h, sQh + q_off + kc * 32);
            LDSM4(a_l, sQl + q_off + kc * 32);
#pragma unroll
            for (int nb = 0; nb < 4; nb++) {
                uint32_t b_h[4], b_l[4];
                uint32_t ka = sK + (uint32_t)(nb * 16) * SP * 2 + k_loff + kc * 32;
                LDSM4(b_h, ka);
                LDSM4(b_l, ka + KVB);
                MMA_BF16(sacc[2*nb],   a_h, &b_h[0]);
                MMA_BF16(sacc[2*nb],   a_h, &b_l[0]);
                MMA_BF16(sacc[2*nb],   a_l, &b_h[0]);
                MMA_BF16(sacc[2*nb+1], a_h, &b_h[2]);
                MMA_BF16(sacc[2*nb+1], a_h, &b_l[2]);
                MMA_BF16(sacc[2*nb+1], a_l, &b_h[2]);
            }
        }

        // ---- online softmax (base-2)
        const int grow0 = qb * 128 + wm + (lane >> 2);
        const bool diag = (kb >= 2 * qb);
        float rmx0 = -1e30f, rmx1 = -1e30f;
#pragma unroll
        for (int j = 0; j < 8; j++) {
            int cbase = kb * 64 + j * 8 + 2 * (lane & 3);
#pragma unroll
            for (int e = 0; e < 2; e++) {
                float t0 = sacc[j][e] * SC2;
                float t1 = sacc[j][2 + e] * SC2;
                if (diag) {
                    if (cbase + e > grow0)     t0 = -1e30f;
                    if (cbase + e > grow0 + 8) t1 = -1e30f;
                }
                sacc[j][e] = t0; sacc[j][2 + e] = t1;
                rmx0 = fmaxf(rmx0, t0); rmx1 = fmaxf(rmx1, t1);
            }
        }
        rmx0 = fmaxf(rmx0, __shfl_xor_sync(0xffffffffu, rmx0, 1));
        rmx0 = fmaxf(rmx0, __shfl_xor_sync(0xffffffffu, rmx0, 2));
        rmx1 = fmaxf(rmx1, __shfl_xor_sync(0xffffffffu, rmx1, 1));
        rmx1 = fmaxf(rmx1, __shfl_xor_sync(0xffffffffu, rmx1, 2));
        float mn0 = fmaxf(m2[0], rmx0), mn1 = fmaxf(m2[1], rmx1);

        float rs0 = 0.f, rs1 = 0.f;
#pragma unroll
        for (int j = 0; j < 8; j++) {
#pragma unroll
            for (int e = 0; e < 2; e++) {
                float p0 = ex2f(sacc[j][e] - mn0);
                float p1 = ex2f(sacc[j][2 + e] - mn1);
                sacc[j][e] = p0; sacc[j][2 + e] = p1;
                rs0 += p0; rs1 += p1;
            }
        }
        rs0 += __shfl_xor_sync(0xffffffffu, rs0, 1);
        rs0 += __shfl_xor_sync(0xffffffffu, rs0, 2);
        rs1 += __shfl_xor_sync(0xffffffffu, rs1, 1);
        rs1 += __shfl_xor_sync(0xffffffffu, rs1, 2);

        float al0 = ex2f(m2[0] - mn0), al1 = ex2f(m2[1] - mn1);
        l[0] = l[0] * al0 + rs0;
        l[1] = l[1] * al1 + rs1;
        m2[0] = mn0; m2[1] = mn1;
#pragma unroll
        for (int j = 0; j < 8; j++) {
            oacc[j][0] *= al0; oacc[j][1] *= al0;
            oacc[j][2] *= al1; oacc[j][3] *= al1;
        }

        // ---- O += P V (P re-split to bf16 hi/lo in registers)
#pragma unroll
        for (int g = 0; g < 4; g++) {
            uint32_t pa_h[4], pa_l[4];
            split2(sacc[2*g][0],   sacc[2*g][1],   pa_h[0], pa_l[0]);
            split2(sacc[2*g][2],   sacc[2*g][3],   pa_h[1], pa_l[1]);
            split2(sacc[2*g+1][0], sacc[2*g+1][1], pa_h[2], pa_l[2]);
            split2(sacc[2*g+1][2], sacc[2*g+1][3], pa_h[3], pa_l[3]);
#pragma unroll
            for (int nb = 0; nb < 4; nb++) {
                uint32_t vb_h[4], vb_l[4];
                uint32_t va = sV + (uint32_t)(g * 16) * SP * 2 + v_loff + nb * 32;
                LDSM4T(vb_h, va);
                LDSM4T(vb_l, va + KVB);
                MMA_BF16(oacc[2*nb],   pa_h, &vb_h[0]);
                MMA_BF16(oacc[2*nb],   pa_h, &vb_l[0]);
                MMA_BF16(oacc[2*nb],   pa_l, &vb_h[0]);
                MMA_BF16(oacc[2*nb+1], pa_h, &vb_h[2]);
                MMA_BF16(oacc[2*nb+1], pa_h, &vb_l[2]);
                MMA_BF16(oacc[2*nb+1], pa_l, &vb_h[2]);
            }
        }
        __syncthreads();   // all warps done with stage kb before it is reloaded
    }
#undef LOAD_KV

    // ---- epilogue: normalize, split, store bf16 hi/lo
    float inv0 = 1.f / l[0], inv1 = 1.f / l[1];
    const size_t row0 = rowbase + (size_t)qb * 128 + wm + (lane >> 2);
#pragma unroll
    for (int j = 0; j < 8; j++) {
        const int col = hoff + j * 8 + 2 * (lane & 3);
        uint32_t hp, lp;
        split2(oacc[j][0] * inv0, oacc[j][1] * inv0, hp, lp);
        *(uint32_t*)((unsigned short*)Ahi + row0 * DM + col) = hp;
        *(uint32_t*)((unsigned short*)Alo + row0 * DM + col) = lp;
        split2(oacc[j][2] * inv1, oacc[j][3] * inv1, hp, lp);
        *(uint32_t*)((unsigned short*)Ahi + (row0 + 8) * DM + col) = hp;
        *(uint32_t*)((unsigned short*)Alo + (row0 + 8) * DM + col) = lp;
    }
}

// ---------------------------------------------------------------------------
extern "C" void kernel_launch(void* const* d_in, const int* in_sizes, int n_in,
                              void* d_out, int out_size)
{
    const float *x, *Wq, *Wk, *Wv, *Wo;
    const int* pos;
    if (in_sizes[0] == MTOT * DM) {            // setup_inputs dict order
        x   = (const float*)d_in[0];
        pos = (const int*)  d_in[1];
        Wq  = (const float*)d_in[2];
        Wk  = (const float*)d_in[3];
        Wv  = (const float*)d_in[4];
        Wo  = (const float*)d_in[5];
    } else {                                   // name-sorted order
        Wk  = (const float*)d_in[0];
        Wo  = (const float*)d_in[1];
        Wq  = (const float*)d_in[2];
        Wv  = (const float*)d_in[3];
        pos = (const int*)  d_in[4];
        x   = (const float*)d_in[5];
    }
    float* out = (float*)d_out;

    float2* cs;
    __nv_bfloat16 *xhi, *xlo, *whi, *wlo, *qhi, *qlo, *khi, *klo, *vhi, *vlo;
    cudaGetSymbolAddress((void**)&cs,  g_cs);
    cudaGetSymbolAddress((void**)&xhi, g_xhi);
    cudaGetSymbolAddress((void**)&xlo, g_xlo);
    cudaGetSymbolAddress((void**)&whi, g_whi);
    cudaGetSymbolAddress((void**)&wlo, g_wlo);
    cudaGetSymbolAddress((void**)&qhi, g_qhi);
    cudaGetSymbolAddress((void**)&qlo, g_qlo);
    cudaGetSymbolAddress((void**)&khi, g_khi);
    cudaGetSymbolAddress((void**)&klo, g_klo);
    cudaGetSymbolAddress((void**)&vhi, g_vhi);
    cudaGetSymbolAddress((void**)&vlo, g_vlo);

    build_cs_kernel<<<(S_ * (DK/2) + 255) / 256, 256>>>(pos, cs);

    const int NX = MTOT * DM, NW = DM * DM;
    split_kernel<<<NX / 8 / 256, 256>>>(x,  xhi, xlo, NX);
    split_kernel<<<NW / 8 / 256, 256>>>(Wq, whi + 0 * (size_t)NW, wlo + 0 * (size_t)NW, NW);
    split_kernel<<<NW / 8 / 256, 256>>>(Wk, whi + 1 * (size_t)NW, wlo + 1 * (size_t)NW, NW);
    split_kernel<<<NW / 8 / 256, 256>>>(Wv, whi + 2 * (size_t)NW, wlo + 2 * (size_t)NW, NW);
    split_kernel<<<NW / 8 / 256, 256>>>(Wo, whi + 3 * (size_t)NW, wlo + 3 * (size_t)NW, NW);

    cudaFuncSetAttribute(gemm_mma<0>, cudaFuncAttributeMaxDynamicSharedMemorySize, GSMEM);
    cudaFuncSetAttribute(gemm_mma<1>, cudaFuncAttributeMaxDynamicSharedMemorySize, GSMEM);
    cudaFuncSetAttribute(gemm_mma<2>, cudaFuncAttributeMaxDynamicSharedMemorySize, GSMEM);
    cudaFuncSetAttribute(attn_mma,    cudaFuncAttributeMaxDynamicSharedMemorySize, ATT_SMEM);

    dim3 gg(DM / 128, MTOT / 128);   // (8, 32)
    gemm_mma<1><<<gg, 256, GSMEM>>>(xhi, xlo, whi + 0 * (size_t)NW, wlo + 0 * (size_t)NW,
                                    nullptr, qhi, qlo, cs);
    gemm_mma<1><<<gg, 256, GSMEM>>>(xhi, xlo, whi + 1 * (size_t)NW, wlo + 1 * (size_t)NW,
                                    nullptr, khi, klo, cs);
    gemm_mma<2><<<gg, 256, GSMEM>>>(xhi, xlo, whi + 2 * (size_t)NW, wlo + 2 * (size_t)NW,
                                    nullptr, vhi, vlo, nullptr);

    attn_mma<<<dim3(16, B_ * NH), 256, ATT_SMEM>>>(qhi, qlo, khi, klo, vhi, vlo, xhi, xlo);

    gemm_mma<0><<<gg, 256, GSMEM>>>(xhi, xlo, whi + 3 * (size_t)NW, wlo + 3 * (size_t)NW,
                                    out, nullptr, nullptr, nullptr);
}

// round 7
// speedup vs baseline: 3.3631x; 1.0610x over previous
#include <cuda_runtime.h>
#include <cuda_bf16.h>
#include <math.h>
#include <stdint.h>

#define DM 1024
#define NH 16
#define DK 64
#define B_ 2
#define S_ 2048
#define MTOT (B_*S_)   // 4096

// ---------------- scratch (device globals: allocation-free) ----------------
__device__ float2 g_cs[S_ * (DK/2)];
__device__ __nv_bfloat16 g_xhi[MTOT*DM];
__device__ __nv_bfloat16 g_xlo[MTOT*DM];
__device__ __nv_bfloat16 g_whi[4][DM*DM];
__device__ __nv_bfloat16 g_wlo[4][DM*DM];
__device__ __nv_bfloat16 g_qhi[MTOT*DM];
__device__ __nv_bfloat16 g_qlo[MTOT*DM];
__device__ __nv_bfloat16 g_khi[MTOT*DM];
__device__ __nv_bfloat16 g_klo[MTOT*DM];
__device__ __nv_bfloat16 g_vhi[MTOT*DM];
__device__ __nv_bfloat16 g_vlo[MTOT*DM];

// ---------------- family-portable PTX helpers ----------------
__device__ __forceinline__ uint32_t smem_u32(const void* p) {
    uint32_t a;
    asm("{ .reg .u64 t; cvta.to.shared.u64 t, %1; cvt.u32.u64 %0, t; }"
        : "=r"(a) : "l"(p));
    return a;
}
#define CP16(saddr, gptr) \
    asm volatile("cp.async.cg.shared.global [%0], [%1], 16;" :: "r"(saddr), "l"(gptr))
#define CPCOMMIT() asm volatile("cp.async.commit_group;" ::: "memory")
#define CPWAIT0()  asm volatile("cp.async.wait_group 0;" ::: "memory")
#define CPWAIT1()  asm volatile("cp.async.wait_group 1;" ::: "memory")
#define LDSM4(r, addr) \
    asm volatile("ldmatrix.sync.aligned.m8n8.x4.shared.b16 {%0,%1,%2,%3}, [%4];" \
        : "=r"((r)[0]), "=r"((r)[1]), "=r"((r)[2]), "=r"((r)[3]) : "r"(addr))
#define LDSM4T(r, addr) \
    asm volatile("ldmatrix.sync.aligned.m8n8.x4.trans.shared.b16 {%0,%1,%2,%3}, [%4];" \
        : "=r"((r)[0]), "=r"((r)[1]), "=r"((r)[2]), "=r"((r)[3]) : "r"(addr))
#define MMA_BF16(d, a, b) \
    asm volatile("mma.sync.aligned.m16n8k16.row.col.f32.bf16.bf16.f32 " \
        "{%0,%1,%2,%3},{%4,%5,%6,%7},{%8,%9},{%0,%1,%2,%3};" \
        : "+f"((d)[0]), "+f"((d)[1]), "+f"((d)[2]), "+f"((d)[3]) \
        : "r"((a)[0]), "r"((a)[1]), "r"((a)[2]), "r"((a)[3]), \
          "r"((b)[0]), "r"((b)[1]))

__device__ __forceinline__ float ex2f(float x) {
    float y; asm("ex2.approx.ftz.f32 %0, %1;" : "=f"(y) : "f"(x)); return y;
}
__device__ __forceinline__ void split2(float v0, float v1, uint32_t& hi, uint32_t& lo) {
    __nv_bfloat16 h0 = __float2bfloat16(v0), h1 = __float2bfloat16(v1);
    __nv_bfloat16 l0 = __float2bfloat16(v0 - __bfloat162float(h0));
    __nv_bfloat16 l1 = __float2bfloat16(v1 - __bfloat162float(h1));
    hi = ((uint32_t)__bfloat16_as_ushort(h1) << 16) | __bfloat16_as_ushort(h0);
    lo = ((uint32_t)__bfloat16_as_ushort(l1) << 16) | __bfloat16_as_ushort(l0);
}

// ---------------------------------------------------------------------------
// cos/sin table
// ---------------------------------------------------------------------------
__global__ void build_cs_kernel(const int* __restrict__ pos, float2* __restrict__ cs)
{
    int idx = blockIdx.x * blockDim.x + threadIdx.x;
    if (idx >= S_ * (DK/2)) return;
    int s = idx >> 5, p = idx & 31;
    float posf = (float)pos[s];
    double e   = (double)(2 * p) / (double)DK;
    float inv  = (float)exp(-e * log(10000.0));
    float ang  = posf * inv;
    cs[idx] = make_float2((float)cos((double)ang), (float)sin((double)ang));
}

// ---------------------------------------------------------------------------
// fp32 -> (bf16 hi, bf16 lo) split
// ---------------------------------------------------------------------------
__global__ void split_kernel(const float* __restrict__ src,
                             __nv_bfloat16* __restrict__ hi,
                             __nv_bfloat16* __restrict__ lo, int n)
{
    int i = (blockIdx.x * blockDim.x + threadIdx.x) * 8;
    if (i >= n) return;
    float4 a = *(const float4*)(src + i);
    float4 b = *(const float4*)(src + i + 4);
    float v[8] = {a.x, a.y, a.z, a.w, b.x, b.y, b.z, b.w};
    uint4 hp, lp;
    uint32_t* hw = (uint32_t*)&hp;
    uint32_t* lw = (uint32_t*)&lp;
#pragma unroll
    for (int j = 0; j < 4; j++) split2(v[2*j], v[2*j+1], hw[j], lw[j]);
    *(uint4*)((unsigned short*)hi + i) = hp;
    *(uint4*)((unsigned short*)lo + i) = lp;
}

// ---------------------------------------------------------------------------
// Split-bf16 tensor-core GEMM: Y = X @ W^T. 128x128 tile, BK=32.
// 4 warps (2m x 2n), warp tile 64x64: 16 LDSM4 per 96 MMAs per k16.
// MMAs ordered in product passes (hh, hl, lh) => dependent spacing 8.
// MODE: 0 = fp32 out, 1 = RoPE + bf16 hi/lo out, 2 = bf16 hi/lo out
// ---------------------------------------------------------------------------
#define BKK 32
#define NKB (DM / BKK)
#define SROW 40
#define TILE_BYTES (128 * SROW * 2)
#define STAGE_BYTES (4 * TILE_BYTES)
#define GSMEM (2 * STAGE_BYTES)

template<int MODE>
__global__ __launch_bounds__(128)
void gemm_mma(const __nv_bfloat16* __restrict__ Ahi, const __nv_bfloat16* __restrict__ Alo,
              const __nv_bfloat16* __restrict__ Bhi, const __nv_bfloat16* __restrict__ Blo,
              float* __restrict__ Y, __nv_bfloat16* __restrict__ Yhi,
              __nv_bfloat16* __restrict__ Ylo, const float2* __restrict__ cs)
{
    extern __shared__ char sm[];
    const uint32_t sb = smem_u32(sm);

    const int tid  = threadIdx.x;
    const int lane = tid & 31;
    const int wid  = tid >> 5;
    const int wm   = (wid & 1) * 64;
    const int wn   = (wid >> 1) * 64;
    const int m0   = blockIdx.y * 128;
    const int n0   = blockIdx.x * 128;

    const __nv_bfloat16* gt[4] = {Ahi, Alo, Bhi, Blo};
    const int rb[4] = {m0, m0, n0, n0};

#define LOAD_STAGE(sidx, kb) do {                                             \
    uint32_t sdst = sb + (sidx) * STAGE_BYTES;                                \
    int kofs = (kb) * BKK;                                                    \
    _Pragma("unroll")                                                         \
    for (int t = 0; t < 4; t++) {                                             \
        _Pragma("unroll")                                                     \
        for (int i = 0; i < 4; i++) {                                         \
            int id = tid + i * 128;                                           \
            int r = id >> 2, c = (id & 3) * 8;                                \
            CP16(sdst + t * TILE_BYTES + (r * SROW + c) * 2,                  \
                 gt[t] + (size_t)(rb[t] + r) * DM + kofs + c);                \
        }                                                                     \
    }                                                                         \
} while (0)

    float acc[4][8][4];
#pragma unroll
    for (int i = 0; i < 4; i++)
#pragma unroll
        for (int j = 0; j < 8; j++)
#pragma unroll
            for (int q = 0; q < 4; q++) acc[i][j][q] = 0.f;

    LOAD_STAGE(0, 0);
    CPCOMMIT();

    for (int kb = 0; kb < NKB; kb++) {
        if (kb + 1 < NKB) { LOAD_STAGE((kb + 1) & 1, kb + 1); CPCOMMIT(); CPWAIT1(); }
        else              { CPWAIT0(); }
        __syncthreads();

        const uint32_t sst = sb + (kb & 1) * STAGE_BYTES;
#pragma unroll
        for (int kk = 0; kk < 2; kk++) {
            uint32_t a_hi[4][4], a_lo[4][4];
            const int ar = wm + (lane & 15);
            const int ac = kk * 16 + (lane >> 4) * 8;
#pragma unroll
            for (int i = 0; i < 4; i++) {
                uint32_t ad = sst + (((ar + i * 16) * SROW + ac) << 1);
                LDSM4(a_hi[i], ad);
                LDSM4(a_lo[i], ad + TILE_BYTES);
            }
            const int br = wn + ((lane >> 4) << 3) + (lane & 7);
            const int bc = kk * 16 + ((lane >> 3) & 1) * 8;
#pragma unroll
            for (int nb = 0; nb < 4; nb++) {
                uint32_t b_h[4], b_l[4];
                uint32_t bd = sst + 2 * TILE_BYTES + (((br + nb * 16) * SROW + bc) << 1);
                LDSM4(b_h, bd);
                LDSM4(b_l, bd + TILE_BYTES);
                // product passes: dependent MMAs to same acc are 8 apart
#pragma unroll
                for (int i = 0; i < 4; i++) {
                    MMA_BF16(acc[i][2*nb],   a_hi[i], &b_h[0]);
                    MMA_BF16(acc[i][2*nb+1], a_hi[i], &b_h[2]);
                }
#pragma unroll
                for (int i = 0; i < 4; i++) {
                    MMA_BF16(acc[i][2*nb],   a_hi[i], &b_l[0]);
                    MMA_BF16(acc[i][2*nb+1], a_hi[i], &b_l[2]);
                }
#pragma unroll
                for (int i = 0; i < 4; i++) {
                    MMA_BF16(acc[i][2*nb],   a_lo[i], &b_h[0]);
                    MMA_BF16(acc[i][2*nb+1], a_lo[i], &b_h[2]);
                }
            }
        }
        __syncthreads();
    }
#undef LOAD_STAGE

#pragma unroll
    for (int i = 0; i < 4; i++)
#pragma unroll
        for (int j = 0; j < 8; j++) {
            const int col = n0 + wn + j * 8 + (lane & 3) * 2;
#pragma unroll
            for (int h = 0; h < 2; h++) {
                const int row = m0 + wm + i * 16 + (lane >> 2) + h * 8;
                float v0 = acc[i][j][h * 2], v1 = acc[i][j][h * 2 + 1];
                if (MODE == 1) {
                    int s = row & (S_ - 1);
                    float2 cp = cs[s * 32 + ((col & (DK - 1)) >> 1)];
                    float o0 = v0 * cp.x - v1 * cp.y;
                    float o1 = v0 * cp.y + v1 * cp.x;
                    v0 = o0; v1 = o1;
                }
                if (MODE == 0) {
                    *(float2*)(Y + (size_t)row * DM + col) = make_float2(v0, v1);
                } else {
                    uint32_t hp, lp;
                    split2(v0, v1, hp, lp);
                    *(uint32_t*)((unsigned short*)Yhi + (size_t)row * DM + col) = hp;
                    *(uint32_t*)((unsigned short*)Ylo + (size_t)row * DM + col) = lp;
                }
            }
        }
}

// ---------------------------------------------------------------------------
// Tensor-core causal flash attention, split bf16.
// CTA = 128 queries of one (b,h). 8 warps x 16 rows. Q fragments hoisted to
// registers (loaded once). K/V fragments preloaded per k-chunk; MMAs in
// product passes (dependent spacing 8).
// ---------------------------------------------------------------------------
#define SP 72
#define QBB (128 * SP * 2)
#define KVB (64 * SP * 2)
#define STG (4 * KVB)
#define ATT_SMEM (2 * QBB + 2 * STG)

__global__ __launch_bounds__(256)
void attn_mma(const __nv_bfloat16* __restrict__ Qhi, const __nv_bfloat16* __restrict__ Qlo,
              const __nv_bfloat16* __restrict__ Khi, const __nv_bfloat16* __restrict__ Klo,
              const __nv_bfloat16* __restrict__ Vhi, const __nv_bfloat16* __restrict__ Vlo,
              __nv_bfloat16* __restrict__ Ahi, __nv_bfloat16* __restrict__ Alo)
{
    extern __shared__ char sm[];
    const uint32_t sb = smem_u32(sm);
    const uint32_t sQh = sb, sQl = sb + QBB;
    const uint32_t sStage = sb + 2 * QBB;

    const int tid = threadIdx.x, lane = tid & 31, wid = tid >> 5;
    const int qb = 15 - blockIdx.x;        // heavy blocks first
    const int bh = blockIdx.y;
    const int b = bh >> 4, h = bh & 15;
    const int wm = wid * 16;
    const size_t rowbase = (size_t)b * S_;
    const int hoff = h * DK;

    // Q tile (128 rows) hi/lo
#pragma unroll
    for (int i = 0; i < 4; i++) {
        int id = tid + i * 256;
        int r = id >> 3, c = (id & 7) * 8;
        size_t g = (rowbase + qb * 128 + r) * DM + hoff + c;
        uint32_t so = (r * SP + c) * 2;
        CP16(sQh + so, Qhi + g);
        CP16(sQl + so, Qlo + g);
    }

#define LOAD_KV(sidx, kb_) do {                                               \
    uint32_t dst = sStage + (sidx) * STG;                                     \
    size_t krow0 = rowbase + (size_t)(kb_) * 64;                              \
    _Pragma("unroll")                                                         \
    for (int i = 0; i < 2; i++) {                                             \
        int id = tid + i * 256;                                               \
        int r = id >> 3, c = (id & 7) * 8;                                    \
        size_t g = (krow0 + r) * DM + hoff + c;                               \
        uint32_t so = (r * SP + c) * 2;                                       \
        CP16(dst + 0 * KVB + so, Khi + g);                                    \
        CP16(dst + 1 * KVB + so, Klo + g);                                    \
        CP16(dst + 2 * KVB + so, Vhi + g);                                    \
        CP16(dst + 3 * KVB + so, Vlo + g);                                    \
    }                                                                         \
} while (0)

    LOAD_KV(0, 0);
    CPCOMMIT();

    float m2[2] = {-1e30f, -1e30f}, l[2] = {0.f, 0.f};
    float oacc[8][4];
#pragma unroll
    for (int j = 0; j < 8; j++)
#pragma unroll
        for (int q = 0; q < 4; q++) oacc[j][q] = 0.f;

    uint32_t qf_h[4][4], qf_l[4][4];   // hoisted Q fragments

    const uint32_t q_off  = ((uint32_t)(wm + (lane & 15)) * SP + (lane >> 4) * 8) * 2;
    const uint32_t k_loff = ((uint32_t)(((lane >> 4) << 3) + (lane & 7)) * SP
                             + ((lane >> 3) & 1) * 8) * 2;
    const uint32_t v_loff = ((uint32_t)(lane & 15) * SP + (lane >> 4) * 8) * 2;

    const float SC2 = 0.125f * 1.4426950408889634f;   // scale * log2(e)
    const int nkb = 2 * qb + 2;

    for (int kb = 0; kb < nkb; kb++) {
        if (kb + 1 < nkb) { LOAD_KV((kb + 1) & 1, kb + 1); CPCOMMIT(); CPWAIT1(); }
        else              { CPWAIT0(); }
        __syncthreads();

        if (kb == 0) {
#pragma unroll
            for (int kc = 0; kc < 4; kc++) {
                LDSM4(qf_h[kc], sQh + q_off + kc * 32);
                LDSM4(qf_l[kc], sQl + q_off + kc * 32);
            }
        }

        const uint32_t sK = sStage + (kb & 1) * STG;
        const uint32_t sV = sK + 2 * KVB;

        // ---- S = Q K^T
        float sacc[8][4];
#pragma unroll
        for (int j = 0; j < 8; j++)
#pragma unroll
            for (int q = 0; q < 4; q++) sacc[j][q] = 0.f;

#pragma unroll
        for (int kc = 0; kc < 4; kc++) {
            uint32_t kb_h[4][4], kb_l[4][4];
#pragma unroll
            for (int nb = 0; nb < 4; nb++) {
                uint32_t ka = sK + (uint32_t)(nb * 16) * SP * 2 + k_loff + kc * 32;
                LDSM4(kb_h[nb], ka);
                LDSM4(kb_l[nb], ka + KVB);
            }
#pragma unroll
            for (int nb = 0; nb < 4; nb++) {
                MMA_BF16(sacc[2*nb],   qf_h[kc], &kb_h[nb][0]);
                MMA_BF16(sacc[2*nb+1], qf_h[kc], &kb_h[nb][2]);
            }
#pragma unroll
            for (int nb = 0; nb < 4; nb++) {
                MMA_BF16(sacc[2*nb],   qf_h[kc], &kb_l[nb][0]);
                MMA_BF16(sacc[2*nb+1], qf_h[kc], &kb_l[nb][2]);
            }
#pragma unroll
            for (int nb = 0; nb < 4; nb++) {
                MMA_BF16(sacc[2*nb],   qf_l[kc], &kb_h[nb][0]);
                MMA_BF16(sacc[2*nb+1], qf_l[kc], &kb_h[nb][2]);
            }
        }

        // ---- online softmax (base-2)
        const int grow0 = qb * 128 + wm + (lane >> 2);
        const bool diag = (kb >= 2 * qb);
        float rmx0 = -1e30f, rmx1 = -1e30f;
#pragma unroll
        for (int j = 0; j < 8; j++) {
            int cbase = kb * 64 + j * 8 + 2 * (lane & 3);
#pragma unroll
            for (int e = 0; e < 2; e++) {
                float t0 = sacc[j][e] * SC2;
                float t1 = sacc[j][2 + e] * SC2;
                if (diag) {
                    if (cbase + e > grow0)     t0 = -1e30f;
                    if (cbase + e > grow0 + 8) t1 = -1e30f;
                }
                sacc[j][e] = t0; sacc[j][2 + e] = t1;
                rmx0 = fmaxf(rmx0, t0); rmx1 = fmaxf(rmx1, t1);
            }
        }
        rmx0 = fmaxf(rmx0, __shfl_xor_sync(0xffffffffu, rmx0, 1));
        rmx0 = fmaxf(rmx0, __shfl_xor_sync(0xffffffffu, rmx0, 2));
        rmx1 = fmaxf(rmx1, __shfl_xor_sync(0xffffffffu, rmx1, 1));
        rmx1 = fmaxf(rmx1, __shfl_xor_sync(0xffffffffu, rmx1, 2));
        float mn0 = fmaxf(m2[0], rmx0), mn1 = fmaxf(m2[1], rmx1);

        float rs0 = 0.f, rs1 = 0.f;
#pragma unroll
        for (int j = 0; j < 8; j++) {
#pragma unroll
            for (int e = 0; e < 2; e++) {
                float p0 = ex2f(sacc[j][e] - mn0);
                float p1 = ex2f(sacc[j][2 + e] - mn1);
                sacc[j][e] = p0; sacc[j][2 + e] = p1;
                rs0 += p0; rs1 += p1;
            }
        }
        rs0 += __shfl_xor_sync(0xffffffffu, rs0, 1);
        rs0 += __shfl_xor_sync(0xffffffffu, rs0, 2);
        rs1 += __shfl_xor_sync(0xffffffffu, rs1, 1);
        rs1 += __shfl_xor_sync(0xffffffffu, rs1, 2);

        float al0 = ex2f(m2[0] - mn0), al1 = ex2f(m2[1] - mn1);
        l[0] = l[0] * al0 + rs0;
        l[1] = l[1] * al1 + rs1;
        m2[0] = mn0; m2[1] = mn1;
#pragma unroll
        for (int j = 0; j < 8; j++) {
            oacc[j][0] *= al0; oacc[j][1] *= al0;
            oacc[j][2] *= al1; oacc[j][3] *= al1;
        }

        // ---- O += P V (P re-split to bf16 hi/lo in registers)
#pragma unroll
        for (int g = 0; g < 4; g++) {
            uint32_t pa_h[4], pa_l[4];
            split2(sacc[2*g][0],   sacc[2*g][1],   pa_h[0], pa_l[0]);
            split2(sacc[2*g][2],   sacc[2*g][3],   pa_h[1], pa_l[1]);
            split2(sacc[2*g+1][0], sacc[2*g+1][1], pa_h[2], pa_l[2]);
            split2(sacc[2*g+1][2], sacc[2*g+1][3], pa_h[3], pa_l[3]);
            uint32_t vb_h[4][4], vb_l[4][4];
#pragma unroll
            for (int nb = 0; nb < 4; nb++) {
                uint32_t va = sV + (uint32_t)(g * 16) * SP * 2 + v_loff + nb * 32;
                LDSM4T(vb_h[nb], va);
                LDSM4T(vb_l[nb], va + KVB);
            }
#pragma unroll
            for (int nb = 0; nb < 4; nb++) {
                MMA_BF16(oacc[2*nb],   pa_h, &vb_h[nb][0]);
                MMA_BF16(oacc[2*nb+1], pa_h, &vb_h[nb][2]);
            }
#pragma unroll
            for (int nb = 0; nb < 4; nb++) {
                MMA_BF16(oacc[2*nb],   pa_h, &vb_l[nb][0]);
                MMA_BF16(oacc[2*nb+1], pa_h, &vb_l[nb][2]);
            }
#pragma unroll
            for (int nb = 0; nb < 4; nb++) {
                MMA_BF16(oacc[2*nb],   pa_l, &vb_h[nb][0]);
                MMA_BF16(oacc[2*nb+1], pa_l, &vb_h[nb][2]);
            }
        }
        __syncthreads();   // all warps done with stage kb before reload
    }
#undef LOAD_KV

    // ---- epilogue: normalize, split, store bf16 hi/lo
    float inv0 = 1.f / l[0], inv1 = 1.f / l[1];
    const size_t row0 = rowbase + (size_t)qb * 128 + wm + (lane >> 2);
#pragma unroll
    for (int j = 0; j < 8; j++) {
        const int col = hoff + j * 8 + 2 * (lane & 3);
        uint32_t hp, lp;
        split2(oacc[j][0] * inv0, oacc[j][1] * inv0, hp, lp);
        *(uint32_t*)((unsigned short*)Ahi + row0 * DM + col) = hp;
        *(uint32_t*)((unsigned short*)Alo + row0 * DM + col) = lp;
        split2(oacc[j][2] * inv1, oacc[j][3] * inv1, hp, lp);
        *(uint32_t*)((unsigned short*)Ahi + (row0 + 8) * DM + col) = hp;
        *(uint32_t*)((unsigned short*)Alo + (row0 + 8) * DM + col) = lp;
    }
}

// ---------------------------------------------------------------------------
extern "C" void kernel_launch(void* const* d_in, const int* in_sizes, int n_in,
                              void* d_out, int out_size)
{
    const float *x, *Wq, *Wk, *Wv, *Wo;
    const int* pos;
    if (in_sizes[0] == MTOT * DM) {            // setup_inputs dict order
        x   = (const float*)d_in[0];
        pos = (const int*)  d_in[1];
        Wq  = (const float*)d_in[2];
        Wk  = (const float*)d_in[3];
        Wv  = (const float*)d_in[4];
        Wo  = (const float*)d_in[5];
    } else {                                   // name-sorted order
        Wk  = (const float*)d_in[0];
        Wo  = (const float*)d_in[1];
        Wq  = (const float*)d_in[2];
        Wv  = (const float*)d_in[3];
        pos = (const int*)  d_in[4];
        x   = (const float*)d_in[5];
    }
    float* out = (float*)d_out;

    float2* cs;
    __nv_bfloat16 *xhi, *xlo, *whi, *wlo, *qhi, *qlo, *khi, *klo, *vhi, *vlo;
    cudaGetSymbolAddress((void**)&cs,  g_cs);
    cudaGetSymbolAddress((void**)&xhi, g_xhi);
    cudaGetSymbolAddress((void**)&xlo, g_xlo);
    cudaGetSymbolAddress((void**)&whi, g_whi);
    cudaGetSymbolAddress((void**)&wlo, g_wlo);
    cudaGetSymbolAddress((void**)&qhi, g_qhi);
    cudaGetSymbolAddress((void**)&qlo, g_qlo);
    cudaGetSymbolAddress((void**)&khi, g_khi);
    cudaGetSymbolAddress((void**)&klo, g_klo);
    cudaGetSymbolAddress((void**)&vhi, g_vhi);
    cudaGetSymbolAddress((void**)&vlo, g_vlo);

    build_cs_kernel<<<(S_ * (DK/2) + 255) / 256, 256>>>(pos, cs);

    const int NX = MTOT * DM, NW = DM * DM;
    split_kernel<<<NX / 8 / 256, 256>>>(x,  xhi, xlo, NX);
    split_kernel<<<NW / 8 / 256, 256>>>(Wq, whi + 0 * (size_t)NW, wlo + 0 * (size_t)NW, NW);
    split_kernel<<<NW / 8 / 256, 256>>>(Wk, whi + 1 * (size_t)NW, wlo + 1 * (size_t)NW, NW);
    split_kernel<<<NW / 8 / 256, 256>>>(Wv, whi + 2 * (size_t)NW, wlo + 2 * (size_t)NW, NW);
    split_kernel<<<NW / 8 / 256, 256>>>(Wo, whi + 3 * (size_t)NW, wlo + 3 * (size_t)NW, NW);

    cudaFuncSetAttribute(gemm_mma<0>, cudaFuncAttributeMaxDynamicSharedMemorySize, GSMEM);
    cudaFuncSetAttribute(gemm_mma<1>, cudaFuncAttributeMaxDynamicSharedMemorySize, GSMEM);
    cudaFuncSetAttribute(gemm_mma<2>, cudaFuncAttributeMaxDynamicSharedMemorySize, GSMEM);
    cudaFuncSetAttribute(attn_mma,    cudaFuncAttributeMaxDynamicSharedMemorySize, ATT_SMEM);

    dim3 gg(DM / 128, MTOT / 128);   // (8, 32)
    gemm_mma<1><<<gg, 128, GSMEM>>>(xhi, xlo, whi + 0 * (size_t)NW, wlo + 0 * (size_t)NW,
                                    nullptr, qhi, qlo, cs);
    gemm_mma<1><<<gg, 128, GSMEM>>>(xhi, xlo, whi + 1 * (size_t)NW, wlo + 1 * (size_t)NW,
                                    nullptr, khi, klo, cs);
    gemm_mma<2><<<gg, 128, GSMEM>>>(xhi, xlo, whi + 2 * (size_t)NW, wlo + 2 * (size_t)NW,
                                    nullptr, vhi, vlo, nullptr);

    attn_mma<<<dim3(16, B_ * NH), 256, ATT_SMEM>>>(qhi, qlo, khi, klo, vhi, vlo, xhi, xlo);

    gemm_mma<0><<<gg, 128, GSMEM>>>(xhi, xlo, whi + 3 * (size_t)NW, wlo + 3 * (size_t)NW,
                                    out, nullptr, nullptr, nullptr);
}

// round 8
// speedup vs baseline: 3.6602x; 1.0883x over previous
#include <cuda_runtime.h>
#include <cuda_bf16.h>
#include <math.h>
#include <stdint.h>

#define DM 1024
#define NH 16
#define DK 64
#define B_ 2
#define S_ 2048
#define MTOT (B_*S_)   // 4096

// ---------------- scratch (device globals: allocation-free) ----------------
__device__ float2 g_cs[S_ * (DK/2)];
__device__ __nv_bfloat16 g_xhi[MTOT*DM];
__device__ __nv_bfloat16 g_xlo[MTOT*DM];
__device__ __nv_bfloat16 g_whi[4][DM*DM];
__device__ __nv_bfloat16 g_wlo[4][DM*DM];
__device__ __nv_bfloat16 g_qhi[MTOT*DM];
__device__ __nv_bfloat16 g_qlo[MTOT*DM];
__device__ __nv_bfloat16 g_khi[MTOT*DM];
__device__ __nv_bfloat16 g_klo[MTOT*DM];
__device__ __nv_bfloat16 g_vhi[MTOT*DM];
__device__ __nv_bfloat16 g_vlo[MTOT*DM];

// ---------------- family-portable PTX helpers ----------------
__device__ __forceinline__ uint32_t smem_u32(const void* p) {
    uint32_t a;
    asm("{ .reg .u64 t; cvta.to.shared.u64 t, %1; cvt.u32.u64 %0, t; }"
        : "=r"(a) : "l"(p));
    return a;
}
#define CP16(saddr, gptr) \
    asm volatile("cp.async.cg.shared.global [%0], [%1], 16;" :: "r"(saddr), "l"(gptr))
#define CPCOMMIT() asm volatile("cp.async.commit_group;" ::: "memory")
#define CPWAIT0()  asm volatile("cp.async.wait_group 0;" ::: "memory")
#define CPWAIT1()  asm volatile("cp.async.wait_group 1;" ::: "memory")
#define LDSM4(r, addr) \
    asm volatile("ldmatrix.sync.aligned.m8n8.x4.shared.b16 {%0,%1,%2,%3}, [%4];" \
        : "=r"((r)[0]), "=r"((r)[1]), "=r"((r)[2]), "=r"((r)[3]) : "r"(addr))
#define LDSM4T(r, addr) \
    asm volatile("ldmatrix.sync.aligned.m8n8.x4.trans.shared.b16 {%0,%1,%2,%3}, [%4];" \
        : "=r"((r)[0]), "=r"((r)[1]), "=r"((r)[2]), "=r"((r)[3]) : "r"(addr))
#define MMA_BF16(d, a, b) \
    asm volatile("mma.sync.aligned.m16n8k16.row.col.f32.bf16.bf16.f32 " \
        "{%0,%1,%2,%3},{%4,%5,%6,%7},{%8,%9},{%0,%1,%2,%3};" \
        : "+f"((d)[0]), "+f"((d)[1]), "+f"((d)[2]), "+f"((d)[3]) \
        : "r"((a)[0]), "r"((a)[1]), "r"((a)[2]), "r"((a)[3]), \
          "r"((b)[0]), "r"((b)[1]))

__device__ __forceinline__ float ex2f(float x) {
    float y; asm("ex2.approx.ftz.f32 %0, %1;" : "=f"(y) : "f"(x)); return y;
}
// fast packed split: fp32 pair -> bf16x2 hi + bf16x2 lo (round-to-nearest)
__device__ __forceinline__ void split2(float v0, float v1, uint32_t& hi, uint32_t& lo) {
    uint32_t h;
    asm("cvt.rn.bf16x2.f32 %0, %1, %2;" : "=r"(h) : "f"(v1), "f"(v0));
    float h0 = __uint_as_float(h << 16);
    float h1 = __uint_as_float(h & 0xffff0000u);
    asm("cvt.rn.bf16x2.f32 %0, %1, %2;" : "=r"(lo) : "f"(v1 - h1), "f"(v0 - h0));
    hi = h;
}

#define SC2A (0.125f * 1.4426950408889634f)   // folded into Q at projection time

// ---------------------------------------------------------------------------
// cos/sin table
// ---------------------------------------------------------------------------
__global__ void build_cs_kernel(const int* __restrict__ pos, float2* __restrict__ cs)
{
    int idx = blockIdx.x * blockDim.x + threadIdx.x;
    if (idx >= S_ * (DK/2)) return;
    int s = idx >> 5, p = idx & 31;
    float posf = (float)pos[s];
    double e   = (double)(2 * p) / (double)DK;
    float inv  = (float)exp(-e * log(10000.0));
    float ang  = posf * inv;
    cs[idx] = make_float2((float)cos((double)ang), (float)sin((double)ang));
}

// ---------------------------------------------------------------------------
// fp32 -> (bf16 hi, bf16 lo) splits
// ---------------------------------------------------------------------------
__global__ void split_kernel(const float* __restrict__ src,
                             __nv_bfloat16* __restrict__ hi,
                             __nv_bfloat16* __restrict__ lo, int n)
{
    int i = (blockIdx.x * blockDim.x + threadIdx.x) * 8;
    if (i >= n) return;
    float4 a = *(const float4*)(src + i);
    float4 b = *(const float4*)(src + i + 4);
    float v[8] = {a.x, a.y, a.z, a.w, b.x, b.y, b.z, b.w};
    uint4 hp, lp;
    uint32_t* hw = (uint32_t*)&hp;
    uint32_t* lw = (uint32_t*)&lp;
#pragma unroll
    for (int j = 0; j < 4; j++) split2(v[2*j], v[2*j+1], hw[j], lw[j]);
    *(uint4*)((unsigned short*)hi + i) = hp;
    *(uint4*)((unsigned short*)lo + i) = lp;
}

// all 4 weight matrices in one launch: gid>>17 selects the weight
__global__ void split_w_kernel(const float* __restrict__ Wq, const float* __restrict__ Wk,
                               const float* __restrict__ Wv, const float* __restrict__ Wo,
                               __nv_bfloat16* __restrict__ whi, __nv_bfloat16* __restrict__ wlo)
{
    int gid = blockIdx.x * blockDim.x + threadIdx.x;   // 0 .. 4*DM*DM/8-1
    int w = gid >> 17;                                 // DM*DM/8 = 131072
    size_t i = (size_t)(gid & 131071) * 8;
    const float* src = (w == 0) ? Wq : (w == 1) ? Wk : (w == 2) ? Wv : Wo;
    size_t base = (size_t)w * DM * DM + i;
    float4 a = *(const float4*)(src + i);
    float4 b = *(const float4*)(src + i + 4);
    float v[8] = {a.x, a.y, a.z, a.w, b.x, b.y, b.z, b.w};
    uint4 hp, lp;
    uint32_t* hw = (uint32_t*)&hp;
    uint32_t* lw = (uint32_t*)&lp;
#pragma unroll
    for (int j = 0; j < 4; j++) split2(v[2*j], v[2*j+1], hw[j], lw[j]);
    *(uint4*)((unsigned short*)whi + base) = hp;
    *(uint4*)((unsigned short*)wlo + base) = lp;
}

// ---------------------------------------------------------------------------
// Split-bf16 tensor-core GEMM core. 128x128 tile, BK=32, 4 warps (64x64 each).
// ---------------------------------------------------------------------------
#define BKK 32
#define NKB (DM / BKK)
#define SROW 40
#define TILE_BYTES (128 * SROW * 2)
#define STAGE_BYTES (4 * TILE_BYTES)
#define GSMEM (2 * STAGE_BYTES)

#define GEMM_PROLOG()                                                         \
    extern __shared__ char sm[];                                              \
    const uint32_t sb = smem_u32(sm);                                         \
    const int tid  = threadIdx.x;                                             \
    const int lane = tid & 31;                                                \
    const int wid  = tid >> 5;                                                \
    const int wm   = (wid & 1) * 64;                                          \
    const int wn   = (wid >> 1) * 64;                                         \
    const int m0   = blockIdx.y * 128;                                        \
    const int n0   = blockIdx.x * 128;

#define LOAD_STAGE(sidx, kb) do {                                             \
    uint32_t sdst = sb + (sidx) * STAGE_BYTES;                                \
    int kofs = (kb) * BKK;                                                    \
    _Pragma("unroll")                                                         \
    for (int t = 0; t < 4; t++) {                                             \
        _Pragma("unroll")                                                     \
        for (int i = 0; i < 4; i++) {                                         \
            int id = tid + i * 128;                                           \
            int r = id >> 2, c = (id & 3) * 8;                                \
            CP16(sdst + t * TILE_BYTES + (r * SROW + c) * 2,                  \
                 gt[t] + (size_t)(rb[t] + r) * DM + kofs + c);                \
        }                                                                     \
    }                                                                         \
} while (0)

#define GEMM_MAIN()                                                           \
    float acc[4][8][4];                                                       \
    _Pragma("unroll")                                                         \
    for (int i = 0; i < 4; i++)                                               \
        _Pragma("unroll")                                                     \
        for (int j = 0; j < 8; j++)                                           \
            _Pragma("unroll")                                                 \
            for (int q = 0; q < 4; q++) acc[i][j][q] = 0.f;                   \
    LOAD_STAGE(0, 0);                                                         \
    CPCOMMIT();                                                               \
    for (int kb = 0; kb < NKB; kb++) {                                        \
        if (kb + 1 < NKB) { LOAD_STAGE((kb + 1) & 1, kb + 1); CPCOMMIT(); CPWAIT1(); } \
        else              { CPWAIT0(); }                                     \
        __syncthreads();                                                      \
        const uint32_t sst = sb + (kb & 1) * STAGE_BYTES;                     \
        _Pragma("unroll")                                                     \
        for (int kk = 0; kk < 2; kk++) {                                      \
            uint32_t a_hi[4][4], a_lo[4][4];                                  \
            const int ar = wm + (lane & 15);                                  \
            const int ac = kk * 16 + (lane >> 4) * 8;                         \
            _Pragma("unroll")                                                 \
            for (int i = 0; i < 4; i++) {                                     \
                uint32_t ad = sst + (((ar + i * 16) * SROW + ac) << 1);       \
                LDSM4(a_hi[i], ad);                                           \
                LDSM4(a_lo[i], ad + TILE_BYTES);                              \
            }                                                                 \
            const int br = wn + ((lane >> 4) << 3) + (lane & 7);              \
            const int bc = kk * 16 + ((lane >> 3) & 1) * 8;                   \
            _Pragma("unroll")                                                 \
            for (int nb = 0; nb < 4; nb++) {                                  \
                uint32_t b_h[4], b_l[4];                                      \
                uint32_t bd = sst + 2 * TILE_BYTES + (((br + nb * 16) * SROW + bc) << 1); \
                LDSM4(b_h, bd);                                               \
                LDSM4(b_l, bd + TILE_BYTES);                                  \
                _Pragma("unroll")                                             \
                for (int i = 0; i < 4; i++) {                                 \
                    MMA_BF16(acc[i][2*nb],   a_hi[i], &b_h[0]);               \
                    MMA_BF16(acc[i][2*nb+1], a_hi[i], &b_h[2]);               \
                }                                                             \
                _Pragma("unroll")                                             \
                for (int i = 0; i < 4; i++) {                                 \
                    MMA_BF16(acc[i][2*nb],   a_hi[i], &b_l[0]);               \
                    MMA_BF16(acc[i][2*nb+1], a_hi[i], &b_l[2]);               \
                }                                                             \
                _Pragma("unroll")                                             \
                for (int i = 0; i < 4; i++) {                                 \
                    MMA_BF16(acc[i][2*nb],   a_lo[i], &b_h[0]);               \
                    MMA_BF16(acc[i][2*nb+1], a_lo[i], &b_h[2]);               \
                }                                                             \
            }                                                                 \
        }                                                                     \
        __syncthreads();                                                      \
    }

// ---- QKV projections in ONE launch: blockIdx.z = 0(Q,rope*scale) 1(K,rope) 2(V)
__global__ __launch_bounds__(128)
void gemm_qkv(const __nv_bfloat16* __restrict__ Xhi, const __nv_bfloat16* __restrict__ Xlo,
              const __nv_bfloat16* __restrict__ Whi, const __nv_bfloat16* __restrict__ Wlo,
              __nv_bfloat16* __restrict__ qhi, __nv_bfloat16* __restrict__ qlo,
              __nv_bfloat16* __restrict__ khi, __nv_bfloat16* __restrict__ klo,
              __nv_bfloat16* __restrict__ vhi, __nv_bfloat16* __restrict__ vlo,
              const float2* __restrict__ cs)
{
    GEMM_PROLOG();
    const int z = blockIdx.z;
    const __nv_bfloat16* gt[4] = {Xhi, Xlo, Whi + (size_t)z * DM * DM, Wlo + (size_t)z * DM * DM};
    const int rb[4] = {m0, m0, n0, n0};
    GEMM_MAIN();

    __nv_bfloat16* Yhi = (z == 0) ? qhi : (z == 1) ? khi : vhi;
    __nv_bfloat16* Ylo = (z == 0) ? qlo : (z == 1) ? klo : vlo;
#pragma unroll
    for (int i = 0; i < 4; i++)
#pragma unroll
        for (int j = 0; j < 8; j++) {
            const int col = n0 + wn + j * 8 + (lane & 3) * 2;
#pragma unroll
            for (int h = 0; h < 2; h++) {
                const int row = m0 + wm + i * 16 + (lane >> 2) + h * 8;
                float v0 = acc[i][j][h * 2], v1 = acc[i][j][h * 2 + 1];
                if (z < 2) {   // RoPE
                    int s = row & (S_ - 1);
                    float2 cp = cs[s * 32 + ((col & (DK - 1)) >> 1)];
                    float o0 = v0 * cp.x - v1 * cp.y;
                    float o1 = v0 * cp.y + v1 * cp.x;
                    v0 = o0; v1 = o1;
                }
                if (z == 0) { v0 *= SC2A; v1 *= SC2A; }  // fold attn scale*log2e into Q
                uint32_t hp, lp;
                split2(v0, v1, hp, lp);
                *(uint32_t*)((unsigned short*)Yhi + (size_t)row * DM + col) = hp;
                *(uint32_t*)((unsigned short*)Ylo + (size_t)row * DM + col) = lp;
            }
        }
}

// ---- O projection: fp32 out
__global__ __launch_bounds__(128)
void gemm_o(const __nv_bfloat16* __restrict__ Xhi, const __nv_bfloat16* __restrict__ Xlo,
            const __nv_bfloat16* __restrict__ Whi, const __nv_bfloat16* __restrict__ Wlo,
            float* __restrict__ Y)
{
    GEMM_PROLOG();
    const __nv_bfloat16* gt[4] = {Xhi, Xlo, Whi, Wlo};
    const int rb[4] = {m0, m0, n0, n0};
    GEMM_MAIN();

#pragma unroll
    for (int i = 0; i < 4; i++)
#pragma unroll
        for (int j = 0; j < 8; j++) {
            const int col = n0 + wn + j * 8 + (lane & 3) * 2;
#pragma unroll
            for (int h = 0; h < 2; h++) {
                const int row = m0 + wm + i * 16 + (lane >> 2) + h * 8;
                *(float2*)(Y + (size_t)row * DM + col) =
                    make_float2(acc[i][j][h * 2], acc[i][j][h * 2 + 1]);
            }
        }
}

// ---------------------------------------------------------------------------
// Tensor-core causal flash attention, split bf16. Q pre-scaled by 0.125*log2e.
// ---------------------------------------------------------------------------
#define SP 72
#define QBB (128 * SP * 2)
#define KVB (64 * SP * 2)
#define STG (4 * KVB)
#define ATT_SMEM (2 * QBB + 2 * STG)

__global__ __launch_bounds__(256)
void attn_mma(const __nv_bfloat16* __restrict__ Qhi, const __nv_bfloat16* __restrict__ Qlo,
              const __nv_bfloat16* __restrict__ Khi, const __nv_bfloat16* __restrict__ Klo,
              const __nv_bfloat16* __restrict__ Vhi, const __nv_bfloat16* __restrict__ Vlo,
              __nv_bfloat16* __restrict__ Ahi, __nv_bfloat16* __restrict__ Alo)
{
    extern __shared__ char sm[];
    const uint32_t sb = smem_u32(sm);
    const uint32_t sQh = sb, sQl = sb + QBB;
    const uint32_t sStage = sb + 2 * QBB;

    const int tid = threadIdx.x, lane = tid & 31, wid = tid >> 5;
    const int qb = 15 - blockIdx.x;        // heavy blocks first
    const int bh = blockIdx.y;
    const int b = bh >> 4, h = bh & 15;
    const int wm = wid * 16;
    const size_t rowbase = (size_t)b * S_;
    const int hoff = h * DK;

#pragma unroll
    for (int i = 0; i < 4; i++) {
        int id = tid + i * 256;
        int r = id >> 3, c = (id & 7) * 8;
        size_t g = (rowbase + qb * 128 + r) * DM + hoff + c;
        uint32_t so = (r * SP + c) * 2;
        CP16(sQh + so, Qhi + g);
        CP16(sQl + so, Qlo + g);
    }

#define LOAD_KV(sidx, kb_) do {                                               \
    uint32_t dst = sStage + (sidx) * STG;                                     \
    size_t krow0 = rowbase + (size_t)(kb_) * 64;                              \
    _Pragma("unroll")                                                         \
    for (int i = 0; i < 2; i++) {                                             \
        int id = tid + i * 256;                                               \
        int r = id >> 3, c = (id & 7) * 8;                                    \
        size_t g = (krow0 + r) * DM + hoff + c;                               \
        uint32_t so = (r * SP + c) * 2;                                       \
        CP16(dst + 0 * KVB + so, Khi + g);                                    \
        CP16(dst + 1 * KVB + so, Klo + g);                                    \
        CP16(dst + 2 * KVB + so, Vhi + g);                                    \
        CP16(dst + 3 * KVB + so, Vlo + g);                                    \
    }                                                                         \
} while (0)

    LOAD_KV(0, 0);
    CPCOMMIT();

    float m2[2] = {-1e30f, -1e30f}, l[2] = {0.f, 0.f};
    float oacc[8][4];
#pragma unroll
    for (int j = 0; j < 8; j++)
#pragma unroll
        for (int q = 0; q < 4; q++) oacc[j][q] = 0.f;

    uint32_t qf_h[4][4], qf_l[4][4];

    const uint32_t q_off  = ((uint32_t)(wm + (lane & 15)) * SP + (lane >> 4) * 8) * 2;
    const uint32_t k_loff = ((uint32_t)(((lane >> 4) << 3) + (lane & 7)) * SP
                             + ((lane >> 3) & 1) * 8) * 2;
    const uint32_t v_loff = ((uint32_t)(lane & 15) * SP + (lane >> 4) * 8) * 2;

    const int nkb = 2 * qb + 2;

    for (int kb = 0; kb < nkb; kb++) {
        if (kb + 1 < nkb) { LOAD_KV((kb + 1) & 1, kb + 1); CPCOMMIT(); CPWAIT1(); }
        else              { CPWAIT0(); }
        __syncthreads();

        if (kb == 0) {
#pragma unroll
            for (int kc = 0; kc < 4; kc++) {
                LDSM4(qf_h[kc], sQh + q_off + kc * 32);
                LDSM4(qf_l[kc], sQl + q_off + kc * 32);
            }
        }

        const uint32_t sK = sStage + (kb & 1) * STG;
        const uint32_t sV = sK + 2 * KVB;

        // ---- S = Q K^T (Q pre-scaled)
        float sacc[8][4];
#pragma unroll
        for (int j = 0; j < 8; j++)
#pragma unroll
            for (int q = 0; q < 4; q++) sacc[j][q] = 0.f;

#pragma unroll
        for (int kc = 0; kc < 4; kc++) {
            uint32_t kb_h[4][4], kb_l[4][4];
#pragma unroll
            for (int nb = 0; nb < 4; nb++) {
                uint32_t ka = sK + (uint32_t)(nb * 16) * SP * 2 + k_loff + kc * 32;
                LDSM4(kb_h[nb], ka);
                LDSM4(kb_l[nb], ka + KVB);
            }
#pragma unroll
            for (int nb = 0; nb < 4; nb++) {
                MMA_BF16(sacc[2*nb],   qf_h[kc], &kb_h[nb][0]);
                MMA_BF16(sacc[2*nb+1], qf_h[kc], &kb_h[nb][2]);
            }
#pragma unroll
            for (int nb = 0; nb < 4; nb++) {
                MMA_BF16(sacc[2*nb],   qf_h[kc], &kb_l[nb][0]);
                MMA_BF16(sacc[2*nb+1], qf_h[kc], &kb_l[nb][2]);
            }
#pragma unroll
            for (int nb = 0; nb < 4; nb++) {
                MMA_BF16(sacc[2*nb],   qf_l[kc], &kb_h[nb][0]);
                MMA_BF16(sacc[2*nb+1], qf_l[kc], &kb_h[nb][2]);
            }
        }

        // ---- online softmax (base-2; scale already in Q)
        const int grow0 = qb * 128 + wm + (lane >> 2);
        const bool diag = (kb >= 2 * qb);
        float rmx0 = -1e30f, rmx1 = -1e30f;
        if (diag) {
#pragma unroll
            for (int j = 0; j < 8; j++) {
                int cbase = kb * 64 + j * 8 + 2 * (lane & 3);
#pragma unroll
                for (int e = 0; e < 2; e++) {
                    if (cbase + e > grow0)     sacc[j][e]     = -1e30f;
                    if (cbase + e > grow0 + 8) sacc[j][2 + e] = -1e30f;
                }
            }
        }
#pragma unroll
        for (int j = 0; j < 8; j++) {
            rmx0 = fmaxf(rmx0, fmaxf(sacc[j][0], sacc[j][1]));
            rmx1 = fmaxf(rmx1, fmaxf(sacc[j][2], sacc[j][3]));
        }
        rmx0 = fmaxf(rmx0, __shfl_xor_sync(0xffffffffu, rmx0, 1));
        rmx0 = fmaxf(rmx0, __shfl_xor_sync(0xffffffffu, rmx0, 2));
        rmx1 = fmaxf(rmx1, __shfl_xor_sync(0xffffffffu, rmx1, 1));
        rmx1 = fmaxf(rmx1, __shfl_xor_sync(0xffffffffu, rmx1, 2));
        float mn0 = fmaxf(m2[0], rmx0), mn1 = fmaxf(m2[1], rmx1);

        float rs0 = 0.f, rs1 = 0.f;
#pragma unroll
        for (int j = 0; j < 8; j++) {
#pragma unroll
            for (int e = 0; e < 2; e++) {
                float p0 = ex2f(sacc[j][e] - mn0);
                float p1 = ex2f(sacc[j][2 + e] - mn1);
                sacc[j][e] = p0; sacc[j][2 + e] = p1;
                rs0 += p0; rs1 += p1;
            }
        }
        rs0 += __shfl_xor_sync(0xffffffffu, rs0, 1);
        rs0 += __shfl_xor_sync(0xffffffffu, rs0, 2);
        rs1 += __shfl_xor_sync(0xffffffffu, rs1, 1);
        rs1 += __shfl_xor_sync(0xffffffffu, rs1, 2);

        float al0 = ex2f(m2[0] - mn0), al1 = ex2f(m2[1] - mn1);
        l[0] = l[0] * al0 + rs0;
        l[1] = l[1] * al1 + rs1;
        m2[0] = mn0; m2[1] = mn1;
#pragma unroll
        for (int j = 0; j < 8; j++) {
            oacc[j][0] *= al0; oacc[j][1] *= al0;
            oacc[j][2] *= al1; oacc[j][3] *= al1;
        }

        // ---- O += P V
#pragma unroll
        for (int g = 0; g < 4; g++) {
            uint32_t pa_h[4], pa_l[4];
            split2(sacc[2*g][0],   sacc[2*g][1],   pa_h[0], pa_l[0]);
            split2(sacc[2*g][2],   sacc[2*g][3],   pa_h[1], pa_l[1]);
            split2(sacc[2*g+1][0], sacc[2*g+1][1], pa_h[2], pa_l[2]);
            split2(sacc[2*g+1][2], sacc[2*g+1][3], pa_h[3], pa_l[3]);
            uint32_t vb_h[4][4], vb_l[4][4];
#pragma unroll
            for (int nb = 0; nb < 4; nb++) {
                uint32_t va = sV + (uint32_t)(g * 16) * SP * 2 + v_loff + nb * 32;
                LDSM4T(vb_h[nb], va);
                LDSM4T(vb_l[nb], va + KVB);
            }
#pragma unroll
            for (int nb = 0; nb < 4; nb++) {
                MMA_BF16(oacc[2*nb],   pa_h, &vb_h[nb][0]);
                MMA_BF16(oacc[2*nb+1], pa_h, &vb_h[nb][2]);
            }
#pragma unroll
            for (int nb = 0; nb < 4; nb++) {
                MMA_BF16(oacc[2*nb],   pa_h, &vb_l[nb][0]);
                MMA_BF16(oacc[2*nb+1], pa_h, &vb_l[nb][2]);
            }
#pragma unroll
            for (int nb = 0; nb < 4; nb++) {
                MMA_BF16(oacc[2*nb],   pa_l, &vb_h[nb][0]);
                MMA_BF16(oacc[2*nb+1], pa_l, &vb_h[nb][2]);
            }
        }
        __syncthreads();
    }
#undef LOAD_KV

    float inv0 = 1.f / l[0], inv1 = 1.f / l[1];
    const size_t row0 = rowbase + (size_t)qb * 128 + wm + (lane >> 2);
#pragma unroll
    for (int j = 0; j < 8; j++) {
        const int col = hoff + j * 8 + 2 * (lane & 3);
        uint32_t hp, lp;
        split2(oacc[j][0] * inv0, oacc[j][1] * inv0, hp, lp);
        *(uint32_t*)((unsigned short*)Ahi + row0 * DM + col) = hp;
        *(uint32_t*)((unsigned short*)Alo + row0 * DM + col) = lp;
        split2(oacc[j][2] * inv1, oacc[j][3] * inv1, hp, lp);
        *(uint32_t*)((unsigned short*)Ahi + (row0 + 8) * DM + col) = hp;
        *(uint32_t*)((unsigned short*)Alo + (row0 + 8) * DM + col) = lp;
    }
}

// ---------------------------------------------------------------------------
extern "C" void kernel_launch(void* const* d_in, const int* in_sizes, int n_in,
                              void* d_out, int out_size)
{
    const float *x, *Wq, *Wk, *Wv, *Wo;
    const int* pos;
    if (in_sizes[0] == MTOT * DM) {            // setup_inputs dict order
        x   = (const float*)d_in[0];
        pos = (const int*)  d_in[1];
        Wq  = (const float*)d_in[2];
        Wk  = (const float*)d_in[3];
        Wv  = (const float*)d_in[4];
        Wo  = (const float*)d_in[5];
    } else {                                   // name-sorted order
        Wk  = (const float*)d_in[0];
        Wo  = (const float*)d_in[1];
        Wq  = (const float*)d_in[2];
        Wv  = (const float*)d_in[3];
        pos = (const int*)  d_in[4];
        x   = (const float*)d_in[5];
    }
    float* out = (float*)d_out;

    float2* cs;
    __nv_bfloat16 *xhi, *xlo, *whi, *wlo, *qhi, *qlo, *khi, *klo, *vhi, *vlo;
    cudaGetSymbolAddress((void**)&cs,  g_cs);
    cudaGetSymbolAddress((void**)&xhi, g_xhi);
    cudaGetSymbolAddress((void**)&xlo, g_xlo);
    cudaGetSymbolAddress((void**)&whi, g_whi);
    cudaGetSymbolAddress((void**)&wlo, g_wlo);
    cudaGetSymbolAddress((void**)&qhi, g_qhi);
    cudaGetSymbolAddress((void**)&qlo, g_qlo);
    cudaGetSymbolAddress((void**)&khi, g_khi);
    cudaGetSymbolAddress((void**)&klo, g_klo);
    cudaGetSymbolAddress((void**)&vhi, g_vhi);
    cudaGetSymbolAddress((void**)&vlo, g_vlo);

    const int NX = MTOT * DM, NW = DM * DM;

    // launch order fixed so ncu (-s 5) captures gemm_o
    build_cs_kernel<<<(S_ * (DK/2) + 255) / 256, 256>>>(pos, cs);          // 0
    split_kernel<<<NX / 8 / 256, 256>>>(x, xhi, xlo, NX);                  // 1
    split_w_kernel<<<4 * NW / 8 / 256, 256>>>(Wq, Wk, Wv, Wo, whi, wlo);   // 2

    cudaFuncSetAttribute(gemm_qkv, cudaFuncAttributeMaxDynamicSharedMemorySize, GSMEM);
    cudaFuncSetAttribute(gemm_o,   cudaFuncAttributeMaxDynamicSharedMemorySize, GSMEM);
    cudaFuncSetAttribute(attn_mma, cudaFuncAttributeMaxDynamicSharedMemorySize, ATT_SMEM);

    dim3 gq(DM / 128, MTOT / 128, 3);   // (8, 32, 3)
    gemm_qkv<<<gq, 128, GSMEM>>>(xhi, xlo, whi, wlo,
                                 qhi, qlo, khi, klo, vhi, vlo, cs);        // 3

    attn_mma<<<dim3(16, B_ * NH), 256, ATT_SMEM>>>(qhi, qlo, khi, klo,
                                                   vhi, vlo, xhi, xlo);    // 4

    dim3 gg(DM / 128, MTOT / 128);      // (8, 32)
    gemm_o<<<gg, 128, GSMEM>>>(xhi, xlo, whi + 3 * (size_t)NW,
                               wlo + 3 * (size_t)NW, out);                 // 5 <- profiled
}

// round 9
// speedup vs baseline: 3.6633x; 1.0008x over previous
#include <cuda_runtime.h>
#include <cuda_bf16.h>
#include <math.h>
#include <stdint.h>

#define DM 1024
#define NH 16
#define DK 64
#define B_ 2
#define S_ 2048
#define MTOT (B_*S_)   // 4096

// ---------------- scratch (device globals: allocation-free) ----------------
__device__ float2 g_cs[S_ * (DK/2)];
__device__ __nv_bfloat16 g_xhi[MTOT*DM];
__device__ __nv_bfloat16 g_xlo[MTOT*DM];
__device__ __nv_bfloat16 g_whi[4][DM*DM];
__device__ __nv_bfloat16 g_wlo[4][DM*DM];
__device__ __nv_bfloat16 g_qhi[MTOT*DM];
__device__ __nv_bfloat16 g_qlo[MTOT*DM];
__device__ __nv_bfloat16 g_khi[MTOT*DM];
__device__ __nv_bfloat16 g_klo[MTOT*DM];
__device__ __nv_bfloat16 g_vhi[MTOT*DM];
__device__ __nv_bfloat16 g_vlo[MTOT*DM];

// ---------------- family-portable PTX helpers ----------------
__device__ __forceinline__ uint32_t smem_u32(const void* p) {
    uint32_t a;
    asm("{ .reg .u64 t; cvta.to.shared.u64 t, %1; cvt.u32.u64 %0, t; }"
        : "=r"(a) : "l"(p));
    return a;
}
#define CP16(saddr, gptr) \
    asm volatile("cp.async.cg.shared.global [%0], [%1], 16;" :: "r"(saddr), "l"(gptr))
#define CPCOMMIT() asm volatile("cp.async.commit_group;" ::: "memory")
#define CPWAIT0()  asm volatile("cp.async.wait_group 0;" ::: "memory")
#define CPWAIT1()  asm volatile("cp.async.wait_group 1;" ::: "memory")
#define LDSM4(r, addr) \
    asm volatile("ldmatrix.sync.aligned.m8n8.x4.shared.b16 {%0,%1,%2,%3}, [%4];" \
        : "=r"((r)[0]), "=r"((r)[1]), "=r"((r)[2]), "=r"((r)[3]) : "r"(addr))
#define LDSM4T(r, addr) \
    asm volatile("ldmatrix.sync.aligned.m8n8.x4.trans.shared.b16 {%0,%1,%2,%3}, [%4];" \
        : "=r"((r)[0]), "=r"((r)[1]), "=r"((r)[2]), "=r"((r)[3]) : "r"(addr))
#define MMA_BF16(d, a, b) \
    asm volatile("mma.sync.aligned.m16n8k16.row.col.f32.bf16.bf16.f32 " \
        "{%0,%1,%2,%3},{%4,%5,%6,%7},{%8,%9},{%0,%1,%2,%3};" \
        : "+f"((d)[0]), "+f"((d)[1]), "+f"((d)[2]), "+f"((d)[3]) \
        : "r"((a)[0]), "r"((a)[1]), "r"((a)[2]), "r"((a)[3]), \
          "r"((b)[0]), "r"((b)[1]))

__device__ __forceinline__ float ex2f(float x) {
    float y; asm("ex2.approx.ftz.f32 %0, %1;" : "=f"(y) : "f"(x)); return y;
}
// fast packed split: fp32 pair -> bf16x2 hi + bf16x2 lo (round-to-nearest)
__device__ __forceinline__ void split2(float v0, float v1, uint32_t& hi, uint32_t& lo) {
    uint32_t h;
    asm("cvt.rn.bf16x2.f32 %0, %1, %2;" : "=r"(h) : "f"(v1), "f"(v0));
    float h0 = __uint_as_float(h << 16);
    float h1 = __uint_as_float(h & 0xffff0000u);
    asm("cvt.rn.bf16x2.f32 %0, %1, %2;" : "=r"(lo) : "f"(v1 - h1), "f"(v0 - h0));
    hi = h;
}

#define SC2A (0.125f * 1.4426950408889634f)   // folded into Q at projection time

// ---------------------------------------------------------------------------
// cos/sin table
// ---------------------------------------------------------------------------
__global__ void build_cs_kernel(const int* __restrict__ pos, float2* __restrict__ cs)
{
    int idx = blockIdx.x * blockDim.x + threadIdx.x;
    if (idx >= S_ * (DK/2)) return;
    int s = idx >> 5, p = idx & 31;
    float posf = (float)pos[s];
    double e   = (double)(2 * p) / (double)DK;
    float inv  = (float)exp(-e * log(10000.0));
    float ang  = posf * inv;
    cs[idx] = make_float2((float)cos((double)ang), (float)sin((double)ang));
}

// ---------------------------------------------------------------------------
// fp32 -> (bf16 hi, bf16 lo) splits
// ---------------------------------------------------------------------------
__global__ void split_kernel(const float* __restrict__ src,
                             __nv_bfloat16* __restrict__ hi,
                             __nv_bfloat16* __restrict__ lo, int n)
{
    int i = (blockIdx.x * blockDim.x + threadIdx.x) * 8;
    if (i >= n) return;
    float4 a = *(const float4*)(src + i);
    float4 b = *(const float4*)(src + i + 4);
    float v[8] = {a.x, a.y, a.z, a.w, b.x, b.y, b.z, b.w};
    uint4 hp, lp;
    uint32_t* hw = (uint32_t*)&hp;
    uint32_t* lw = (uint32_t*)&lp;
#pragma unroll
    for (int j = 0; j < 4; j++) split2(v[2*j], v[2*j+1], hw[j], lw[j]);
    *(uint4*)((unsigned short*)hi + i) = hp;
    *(uint4*)((unsigned short*)lo + i) = lp;
}

__global__ void split_w_kernel(const float* __restrict__ Wq, const float* __restrict__ Wk,
                               const float* __restrict__ Wv, const float* __restrict__ Wo,
                               __nv_bfloat16* __restrict__ whi, __nv_bfloat16* __restrict__ wlo)
{
    int gid = blockIdx.x * blockDim.x + threadIdx.x;
    int w = gid >> 17;
    size_t i = (size_t)(gid & 131071) * 8;
    const float* src = (w == 0) ? Wq : (w == 1) ? Wk : (w == 2) ? Wv : Wo;
    size_t base = (size_t)w * DM * DM + i;
    float4 a = *(const float4*)(src + i);
    float4 b = *(const float4*)(src + i + 4);
    float v[8] = {a.x, a.y, a.z, a.w, b.x, b.y, b.z, b.w};
    uint4 hp, lp;
    uint32_t* hw = (uint32_t*)&hp;
    uint32_t* lw = (uint32_t*)&lp;
#pragma unroll
    for (int j = 0; j < 4; j++) split2(v[2*j], v[2*j+1], hw[j], lw[j]);
    *(uint4*)((unsigned short*)whi + base) = hp;
    *(uint4*)((unsigned short*)wlo + base) = lp;
}

// ---------------------------------------------------------------------------
// Split-bf16 tensor-core GEMM core. CTA tile 128x64, BK=32, 4 warps
// (warp tile 64x32, 2m x 2n). Low regs -> 3 CTAs/SM (3 warps/SMSP).
// ---------------------------------------------------------------------------
#define BKK 32
#define NKB (DM / BKK)
#define SROW 40
#define A_TILE (128 * SROW * 2)          // 10240
#define B_TILE (64 * SROW * 2)           // 5120
#define STAGE_BYTES (2 * A_TILE + 2 * B_TILE)   // 30720
#define GSMEM (2 * STAGE_BYTES)          // 61440
#define OFF_AH 0
#define OFF_AL A_TILE
#define OFF_BH (2 * A_TILE)
#define OFF_BL (2 * A_TILE + B_TILE)

#define GEMM_PROLOG()                                                         \
    extern __shared__ char sm[];                                              \
    const uint32_t sb = smem_u32(sm);                                         \
    const int tid  = threadIdx.x;                                             \
    const int lane = tid & 31;                                                \
    const int wid  = tid >> 5;                                                \
    const int wm   = (wid & 1) * 64;                                          \
    const int wn   = (wid >> 1) * 32;                                         \
    const int m0   = blockIdx.y * 128;                                        \
    const int n0   = blockIdx.x * 64;

#define LOAD_STAGE(sidx, kb) do {                                             \
    uint32_t sdst = sb + (sidx) * STAGE_BYTES;                                \
    int kofs = (kb) * BKK;                                                    \
    _Pragma("unroll")                                                         \
    for (int i = 0; i < 4; i++) {                                             \
        int id = tid + i * 128;                                               \
        int r = id >> 2, c = (id & 3) * 8;                                    \
        CP16(sdst + OFF_AH + (r * SROW + c) * 2,                              \
             Ahi_ + (size_t)(m0 + r) * DM + kofs + c);                        \
        CP16(sdst + OFF_AL + (r * SROW + c) * 2,                              \
             Alo_ + (size_t)(m0 + r) * DM + kofs + c);                        \
    }                                                                         \
    _Pragma("unroll")                                                         \
    for (int i = 0; i < 2; i++) {                                             \
        int id = tid + i * 128;                                               \
        int r = id >> 2, c = (id & 3) * 8;                                    \
        CP16(sdst + OFF_BH + (r * SROW + c) * 2,                              \
             Bhi_ + (size_t)(n0 + r) * DM + kofs + c);                        \
        CP16(sdst + OFF_BL + (r * SROW + c) * 2,                              \
             Blo_ + (size_t)(n0 + r) * DM + kofs + c);                        \
    }                                                                         \
} while (0)

#define GEMM_MAIN()                                                           \
    float acc[4][4][4];                                                       \
    _Pragma("unroll")                                                         \
    for (int i = 0; i < 4; i++)                                               \
        _Pragma("unroll")                                                     \
        for (int j = 0; j < 4; j++)                                           \
            _Pragma("unroll")                                                 \
            for (int q = 0; q < 4; q++) acc[i][j][q] = 0.f;                   \
    LOAD_STAGE(0, 0);                                                         \
    CPCOMMIT();                                                               \
    for (int kb = 0; kb < NKB; kb++) {                                        \
        if (kb + 1 < NKB) { LOAD_STAGE((kb + 1) & 1, kb + 1); CPCOMMIT(); CPWAIT1(); } \
        else              { CPWAIT0(); }                                     \
        __syncthreads();                                                      \
        const uint32_t sst = sb + (kb & 1) * STAGE_BYTES;                     \
        _Pragma("unroll")                                                     \
        for (int kk = 0; kk < 2; kk++) {                                      \
            uint32_t a_hi[4][4], a_lo[4][4], b_h[2][4], b_l[2][4];            \
            const int ar = wm + (lane & 15);                                  \
            const int ac = kk * 16 + (lane >> 4) * 8;                         \
            _Pragma("unroll")                                                 \
            for (int i = 0; i < 4; i++) {                                     \
                uint32_t ad = sst + (((ar + i * 16) * SROW + ac) << 1);       \
                LDSM4(a_hi[i], ad + OFF_AH);                                  \
                LDSM4(a_lo[i], ad + OFF_AL);                                  \
            }                                                                 \
            const int br = wn + ((lane >> 4) << 3) + (lane & 7);              \
            const int bc = kk * 16 + ((lane >> 3) & 1) * 8;                   \
            _Pragma("unroll")                                                 \
            for (int nb = 0; nb < 2; nb++) {                                  \
                uint32_t bd = sst + (((br + nb * 16) * SROW + bc) << 1);      \
                LDSM4(b_h[nb], bd + OFF_BH);                                  \
                LDSM4(b_l[nb], bd + OFF_BL);                                  \
            }                                                                 \
            _Pragma("unroll")                                                 \
            for (int nb = 0; nb < 2; nb++)                                    \
                _Pragma("unroll")                                             \
                for (int i = 0; i < 4; i++) {                                 \
                    MMA_BF16(acc[i][2*nb],   a_hi[i], &b_h[nb][0]);           \
                    MMA_BF16(acc[i][2*nb+1], a_hi[i], &b_h[nb][2]);           \
                }                                                             \
            _Pragma("unroll")                                                 \
            for (int nb = 0; nb < 2; nb++)                                    \
                _Pragma("unroll")                                             \
                for (int i = 0; i < 4; i++) {                                 \
                    MMA_BF16(acc[i][2*nb],   a_hi[i], &b_l[nb][0]);           \
                    MMA_BF16(acc[i][2*nb+1], a_hi[i], &b_l[nb][2]);           \
                }                                                             \
            _Pragma("unroll")                                                 \
            for (int nb = 0; nb < 2; nb++)                                    \
                _Pragma("unroll")                                             \
                for (int i = 0; i < 4; i++) {                                 \
                    MMA_BF16(acc[i][2*nb],   a_lo[i], &b_h[nb][0]);           \
                    MMA_BF16(acc[i][2*nb+1], a_lo[i], &b_h[nb][2]);           \
                }                                                             \
        }                                                                     \
        __syncthreads();                                                      \
    }

// ---- QKV projections in ONE launch: blockIdx.z = 0(Q,rope*scale) 1(K,rope) 2(V)
__global__ __launch_bounds__(128, 3)
void gemm_qkv(const __nv_bfloat16* __restrict__ Xhi, const __nv_bfloat16* __restrict__ Xlo,
              const __nv_bfloat16* __restrict__ Whi, const __nv_bfloat16* __restrict__ Wlo,
              __nv_bfloat16* __restrict__ qhi, __nv_bfloat16* __restrict__ qlo,
              __nv_bfloat16* __restrict__ khi, __nv_bfloat16* __restrict__ klo,
              __nv_bfloat16* __restrict__ vhi, __nv_bfloat16* __restrict__ vlo,
              const float2* __restrict__ cs)
{
    GEMM_PROLOG();
    const int z = blockIdx.z;
    const __nv_bfloat16* Ahi_ = Xhi;
    const __nv_bfloat16* Alo_ = Xlo;
    const __nv_bfloat16* Bhi_ = Whi + (size_t)z * DM * DM;
    const __nv_bfloat16* Blo_ = Wlo + (size_t)z * DM * DM;
    GEMM_MAIN();

    __nv_bfloat16* Yhi = (z == 0) ? qhi : (z == 1) ? khi : vhi;
    __nv_bfloat16* Ylo = (z == 0) ? qlo : (z == 1) ? klo : vlo;
#pragma unroll
    for (int i = 0; i < 4; i++)
#pragma unroll
        for (int j = 0; j < 4; j++) {
            const int col = n0 + wn + j * 8 + (lane & 3) * 2;
#pragma unroll
            for (int h = 0; h < 2; h++) {
                const int row = m0 + wm + i * 16 + (lane >> 2) + h * 8;
                float v0 = acc[i][j][h * 2], v1 = acc[i][j][h * 2 + 1];
                if (z < 2) {   // RoPE
                    int s = row & (S_ - 1);
                    float2 cp = cs[s * 32 + ((col & (DK - 1)) >> 1)];
                    float o0 = v0 * cp.x - v1 * cp.y;
                    float o1 = v0 * cp.y + v1 * cp.x;
                    v0 = o0; v1 = o1;
                }
                if (z == 0) { v0 *= SC2A; v1 *= SC2A; }
                uint32_t hp, lp;
                split2(v0, v1, hp, lp);
                *(uint32_t*)((unsigned short*)Yhi + (size_t)row * DM + col) = hp;
                *(uint32_t*)((unsigned short*)Ylo + (size_t)row * DM + col) = lp;
            }
        }
}

// ---- O projection: fp32 out
__global__ __launch_bounds__(128, 3)
void gemm_o(const __nv_bfloat16* __restrict__ Xhi, const __nv_bfloat16* __restrict__ Xlo,
            const __nv_bfloat16* __restrict__ Whi, const __nv_bfloat16* __restrict__ Wlo,
            float* __restrict__ Y)
{
    GEMM_PROLOG();
    const __nv_bfloat16* Ahi_ = Xhi;
    const __nv_bfloat16* Alo_ = Xlo;
    const __nv_bfloat16* Bhi_ = Whi;
    const __nv_bfloat16* Blo_ = Wlo;
    GEMM_MAIN();

#pragma unroll
    for (int i = 0; i < 4; i++)
#pragma unroll
        for (int j = 0; j < 4; j++) {
            const int col = n0 + wn + j * 8 + (lane & 3) * 2;
#pragma unroll
            for (int h = 0; h < 2; h++) {
                const int row = m0 + wm + i * 16 + (lane >> 2) + h * 8;
                *(float2*)(Y + (size_t)row * DM + col) =
                    make_float2(acc[i][j][h * 2], acc[i][j][h * 2 + 1]);
            }
        }
}

// ---------------------------------------------------------------------------
// Tensor-core causal flash attention, split bf16. Q pre-scaled by 0.125*log2e.
// ---------------------------------------------------------------------------
#define SP 72
#define QBB (128 * SP * 2)
#define KVB (64 * SP * 2)
#define STG (4 * KVB)
#define ATT_SMEM (2 * QBB + 2 * STG)

__global__ __launch_bounds__(256)
void attn_mma(const __nv_bfloat16* __restrict__ Qhi, const __nv_bfloat16* __restrict__ Qlo,
              const __nv_bfloat16* __restrict__ Khi, const __nv_bfloat16* __restrict__ Klo,
              const __nv_bfloat16* __restrict__ Vhi, const __nv_bfloat16* __restrict__ Vlo,
              __nv_bfloat16* __restrict__ Ahi, __nv_bfloat16* __restrict__ Alo)
{
    extern __shared__ char sm[];
    const uint32_t sb = smem_u32(sm);
    const uint32_t sQh = sb, sQl = sb + QBB;
    const uint32_t sStage = sb + 2 * QBB;

    const int tid = threadIdx.x, lane = tid & 31, wid = tid >> 5;
    const int qb = 15 - blockIdx.x;
    const int bh = blockIdx.y;
    const int b = bh >> 4, h = bh & 15;
    const int wm = wid * 16;
    const size_t rowbase = (size_t)b * S_;
    const int hoff = h * DK;

#pragma unroll
    for (int i = 0; i < 4; i++) {
        int id = tid + i * 256;
        int r = id >> 3, c = (id & 7) * 8;
        size_t g = (rowbase + qb * 128 + r) * DM + hoff + c;
        uint32_t so = (r * SP + c) * 2;
        CP16(sQh + so, Qhi + g);
        CP16(sQl + so, Qlo + g);
    }

#define LOAD_KV(sidx, kb_) do {                                               \
    uint32_t dst = sStage + (sidx) * STG;                                     \
    size_t krow0 = rowbase + (size_t)(kb_) * 64;                              \
    _Pragma("unroll")                                                         \
    for (int i = 0; i < 2; i++) {                                             \
        int id = tid + i * 256;                                               \
        int r = id >> 3, c = (id & 7) * 8;                                    \
        size_t g = (krow0 + r) * DM + hoff + c;                               \
        uint32_t so = (r * SP + c) * 2;                                       \
        CP16(dst + 0 * KVB + so, Khi + g);                                    \
        CP16(dst + 1 * KVB + so, Klo + g);                                    \
        CP16(dst + 2 * KVB + so, Vhi + g);                                    \
        CP16(dst + 3 * KVB + so, Vlo + g);                                    \
    }                                                                         \
} while (0)

    LOAD_KV(0, 0);
    CPCOMMIT();

    float m2[2] = {-1e30f, -1e30f}, l[2] = {0.f, 0.f};
    float oacc[8][4];
#pragma unroll
    for (int j = 0; j < 8; j++)
#pragma unroll
        for (int q = 0; q < 4; q++) oacc[j][q] = 0.f;

    uint32_t qf_h[4][4], qf_l[4][4];

    const uint32_t q_off  = ((uint32_t)(wm + (lane & 15)) * SP + (lane >> 4) * 8) * 2;
    const uint32_t k_loff = ((uint32_t)(((lane >> 4) << 3) + (lane & 7)) * SP
                             + ((lane >> 3) & 1) * 8) * 2;
    const uint32_t v_loff = ((uint32_t)(lane & 15) * SP + (lane >> 4) * 8) * 2;

    const int nkb = 2 * qb + 2;

    for (int kb = 0; kb < nkb; kb++) {
        if (kb + 1 < nkb) { LOAD_KV((kb + 1) & 1, kb + 1); CPCOMMIT(); CPWAIT1(); }
        else              { CPWAIT0(); }
        __syncthreads();

        if (kb == 0) {
#pragma unroll
            for (int kc = 0; kc < 4; kc++) {
                LDSM4(qf_h[kc], sQh + q_off + kc * 32);
                LDSM4(qf_l[kc], sQl + q_off + kc * 32);
            }
        }

        const uint32_t sK = sStage + (kb & 1) * STG;
        const uint32_t sV = sK + 2 * KVB;

        float sacc[8][4];
#pragma unroll
        for (int j = 0; j < 8; j++)
#pragma unroll
            for (int q = 0; q < 4; q++) sacc[j][q] = 0.f;

#pragma unroll
        for (int kc = 0; kc < 4; kc++) {
            uint32_t kb_h[4][4], kb_l[4][4];
#pragma unroll
            for (int nb = 0; nb < 4; nb++) {
                uint32_t ka = sK + (uint32_t)(nb * 16) * SP * 2 + k_loff + kc * 32;
                LDSM4(kb_h[nb], ka);
                LDSM4(kb_l[nb], ka + KVB);
            }
#pragma unroll
            for (int nb = 0; nb < 4; nb++) {
                MMA_BF16(sacc[2*nb],   qf_h[kc], &kb_h[nb][0]);
                MMA_BF16(sacc[2*nb+1], qf_h[kc], &kb_h[nb][2]);
            }
#pragma unroll
            for (int nb = 0; nb < 4; nb++) {
                MMA_BF16(sacc[2*nb],   qf_h[kc], &kb_l[nb][0]);
                MMA_BF16(sacc[2*nb+1], qf_h[kc], &kb_l[nb][2]);
            }
#pragma unroll
            for (int nb = 0; nb < 4; nb++) {
                MMA_BF16(sacc[2*nb],   qf_l[kc], &kb_h[nb][0]);
                MMA_BF16(sacc[2*nb+1], qf_l[kc], &kb_h[nb][2]);
            }
        }

        const int grow0 = qb * 128 + wm + (lane >> 2);
        const bool diag = (kb >= 2 * qb);
        float rmx0 = -1e30f, rmx1 = -1e30f;
        if (diag) {
#pragma unroll
            for (int j = 0; j < 8; j++) {
                int cbase = kb * 64 + j * 8 + 2 * (lane & 3);
#pragma unroll
                for (int e = 0; e < 2; e++) {
                    if (cbase + e > grow0)     sacc[j][e]     = -1e30f;
                    if (cbase + e > grow0 + 8) sacc[j][2 + e] = -1e30f;
                }
            }
        }
#pragma unroll
        for (int j = 0; j < 8; j++) {
            rmx0 = fmaxf(rmx0, fmaxf(sacc[j][0], sacc[j][1]));
            rmx1 = fmaxf(rmx1, fmaxf(sacc[j][2], sacc[j][3]));
        }
        rmx0 = fmaxf(rmx0, __shfl_xor_sync(0xffffffffu, rmx0, 1));
        rmx0 = fmaxf(rmx0, __shfl_xor_sync(0xffffffffu, rmx0, 2));
        rmx1 = fmaxf(rmx1, __shfl_xor_sync(0xffffffffu, rmx1, 1));
        rmx1 = fmaxf(rmx1, __shfl_xor_sync(0xffffffffu, rmx1, 2));
        float mn0 = fmaxf(m2[0], rmx0), mn1 = fmaxf(m2[1], rmx1);

        float rs0 = 0.f, rs1 = 0.f;
#pragma unroll
        for (int j = 0; j < 8; j++) {
#pragma unroll
            for (int e = 0; e < 2; e++) {
                float p0 = ex2f(sacc[j][e] - mn0);
                float p1 = ex2f(sacc[j][2 + e] - mn1);
                sacc[j][e] = p0; sacc[j][2 + e] = p1;
                rs0 += p0; rs1 += p1;
            }
        }
        rs0 += __shfl_xor_sync(0xffffffffu, rs0, 1);
        rs0 += __shfl_xor_sync(0xffffffffu, rs0, 2);
        rs1 += __shfl_xor_sync(0xffffffffu, rs1, 1);
        rs1 += __shfl_xor_sync(0xffffffffu, rs1, 2);

        float al0 = ex2f(m2[0] - mn0), al1 = ex2f(m2[1] - mn1);
        l[0] = l[0] * al0 + rs0;
        l[1] = l[1] * al1 + rs1;
        m2[0] = mn0; m2[1] = mn1;
#pragma unroll
        for (int j = 0; j < 8; j++) {
            oacc[j][0] *= al0; oacc[j][1] *= al0;
            oacc[j][2] *= al1; oacc[j][3] *= al1;
        }

#pragma unroll
        for (int g = 0; g < 4; g++) {
            uint32_t pa_h[4], pa_l[4];
            split2(sacc[2*g][0],   sacc[2*g][1],   pa_h[0], pa_l[0]);
            split2(sacc[2*g][2],   sacc[2*g][3],   pa_h[1], pa_l[1]);
            split2(sacc[2*g+1][0], sacc[2*g+1][1], pa_h[2], pa_l[2]);
            split2(sacc[2*g+1][2], sacc[2*g+1][3], pa_h[3], pa_l[3]);
            uint32_t vb_h[4][4], vb_l[4][4];
#pragma unroll
            for (int nb = 0; nb < 4; nb++) {
                uint32_t va = sV + (uint32_t)(g * 16) * SP * 2 + v_loff + nb * 32;
                LDSM4T(vb_h[nb], va);
                LDSM4T(vb_l[nb], va + KVB);
            }
#pragma unroll
            for (int nb = 0; nb < 4; nb++) {
                MMA_BF16(oacc[2*nb],   pa_h, &vb_h[nb][0]);
                MMA_BF16(oacc[2*nb+1], pa_h, &vb_h[nb][2]);
            }
#pragma unroll
            for (int nb = 0; nb < 4; nb++) {
                MMA_BF16(oacc[2*nb],   pa_h, &vb_l[nb][0]);
                MMA_BF16(oacc[2*nb+1], pa_h, &vb_l[nb][2]);
            }
#pragma unroll
            for (int nb = 0; nb < 4; nb++) {
                MMA_BF16(oacc[2*nb],   pa_l, &vb_h[nb][0]);
                MMA_BF16(oacc[2*nb+1], pa_l, &vb_h[nb][2]);
            }
        }
        __syncthreads();
    }
#undef LOAD_KV

    float inv0 = 1.f / l[0], inv1 = 1.f / l[1];
    const size_t row0 = rowbase + (size_t)qb * 128 + wm + (lane >> 2);
#pragma unroll
    for (int j = 0; j < 8; j++) {
        const int col = hoff + j * 8 + 2 * (lane & 3);
        uint32_t hp, lp;
        split2(oacc[j][0] * inv0, oacc[j][1] * inv0, hp, lp);
        *(uint32_t*)((unsigned short*)Ahi + row0 * DM + col) = hp;
        *(uint32_t*)((unsigned short*)Alo + row0 * DM + col) = lp;
        split2(oacc[j][2] * inv1, oacc[j][3] * inv1, hp, lp);
        *(uint32_t*)((unsigned short*)Ahi + (row0 + 8) * DM + col) = hp;
        *(uint32_t*)((unsigned short*)Alo + (row0 + 8) * DM + col) = lp;
    }
}

// ---------------------------------------------------------------------------
extern "C" void kernel_launch(void* const* d_in, const int* in_sizes, int n_in,
                              void* d_out, int out_size)
{
    const float *x, *Wq, *Wk, *Wv, *Wo;
    const int* pos;
    if (in_sizes[0] == MTOT * DM) {            // setup_inputs dict order
        x   = (const float*)d_in[0];
        pos = (const int*)  d_in[1];
        Wq  = (const float*)d_in[2];
        Wk  = (const float*)d_in[3];
        Wv  = (const float*)d_in[4];
        Wo  = (const float*)d_in[5];
    } else {                                   // name-sorted order
        Wk  = (const float*)d_in[0];
        Wo  = (const float*)d_in[1];
        Wq  = (const float*)d_in[2];
        Wv  = (const float*)d_in[3];
        pos = (const int*)  d_in[4];
        x   = (const float*)d_in[5];
    }
    float* out = (float*)d_out;

    float2* cs;
    __nv_bfloat16 *xhi, *xlo, *whi, *wlo, *qhi, *qlo, *khi, *klo, *vhi, *vlo;
    cudaGetSymbolAddress((void**)&cs,  g_cs);
    cudaGetSymbolAddress((void**)&xhi, g_xhi);
    cudaGetSymbolAddress((void**)&xlo, g_xlo);
    cudaGetSymbolAddress((void**)&whi, g_whi);
    cudaGetSymbolAddress((void**)&wlo, g_wlo);
    cudaGetSymbolAddress((void**)&qhi, g_qhi);
    cudaGetSymbolAddress((void**)&qlo, g_qlo);
    cudaGetSymbolAddress((void**)&khi, g_khi);
    cudaGetSymbolAddress((void**)&klo, g_klo);
    cudaGetSymbolAddress((void**)&vhi, g_vhi);
    cudaGetSymbolAddress((void**)&vlo, g_vlo);

    const int NX = MTOT * DM, NW = DM * DM;

    build_cs_kernel<<<(S_ * (DK/2) + 255) / 256, 256>>>(pos, cs);          // 0
    split_kernel<<<NX / 8 / 256, 256>>>(x, xhi, xlo, NX);                  // 1
    split_w_kernel<<<4 * NW / 8 / 256, 256>>>(Wq, Wk, Wv, Wo, whi, wlo);   // 2

    cudaFuncSetAttribute(gemm_qkv, cudaFuncAttributeMaxDynamicSharedMemorySize, GSMEM);
    cudaFuncSetAttribute(gemm_o,   cudaFuncAttributeMaxDynamicSharedMemorySize, GSMEM);
    cudaFuncSetAttribute(attn_mma, cudaFuncAttributeMaxDynamicSharedMemorySize, ATT_SMEM);

    dim3 gq(DM / 64, MTOT / 128, 3);    // (16, 32, 3)
    gemm_qkv<<<gq, 128, GSMEM>>>(xhi, xlo, whi, wlo,
                                 qhi, qlo, khi, klo, vhi, vlo, cs);        // 3

    attn_mma<<<dim3(16, B_ * NH), 256, ATT_SMEM>>>(qhi, qlo, khi, klo,
                                                   vhi, vlo, xhi, xlo);    // 4

    dim3 gg(DM / 64, MTOT / 128);       // (16, 32)
    gemm_o<<<gg, 128, GSMEM>>>(xhi, xlo, whi + 3 * (size_t)NW,
                               wlo + 3 * (size_t)NW, out);                 // 5 <- profiled
}